// round 5
// baseline (speedup 1.0000x reference)
#include <cuda_runtime.h>
#include <cstdint>

// Shapes (fixed by the benchmark)
#define B 4
#define L 2048
#define H 8
#define D 64
#define SK 40          // sample_k
#define U 40           // top-k queries kept
#define BH (B*H)       // 32
#define C (H*D)        // 512 columns for cumsum view

// Stage-1 tiling
#define QT 128         // queries per tile
#define NQT (L/QT)     // 16
#define KC 128         // keys per chunk
#define NKC (L/KC)     // 16
#define ECAP 640       // bucket capacity per (tile,chunk); mean 320, sd ~17
#define PQ 68          // Q/K smem pitch (floats)
#define SP 41          // S smem pitch (floats): 41 coprime 32 -> conflict-free finalize

// Attention chunking
#define KCH 128
#define NCHK (L/KCH)   // 16
#define PKS 68
#define PVS 66

// Cumsum chunking
#define NCH 128
#define CHUNK (L/NCH)  // 16

// -------- scratch (device globals; no allocation allowed) --------
__device__ unsigned g_bkt[NQT * NKC * ECAP];
__device__ int      g_bcnt[NQT * NKC];
__device__ float    g_M[BH * L];
__device__ int      g_Mtop[BH * U];
__device__ float    g_pm[BH * U * NCHK];
__device__ float    g_pl[BH * U * NCHK];
__device__ float    g_pacc[BH * U * NCHK * D];
__device__ float    g_csum[B * NCH * C];

// ===================== Stage 1a: bucket sample indices =====================
// idx shared across (b,h). Pack: q[7b]<<13 | s[6b]<<7 | k_local[7b].
__global__ void k_bucket(const int* __restrict__ idx)
{
    __shared__ int scnt[NKC];
    int tile = blockIdx.x, t = threadIdx.x;
    if (t < NKC) scnt[t] = 0;
    __syncthreads();
    for (int i = t; i < QT * SK; i += 256) {
        int q = i / SK, s = i % SK;
        int ki = idx[(tile * QT + q) * SK + s];
        int c = ki >> 7, kl = ki & 127;
        int slot = atomicAdd(&scnt[c], 1);
        if (slot < ECAP)
            g_bkt[(tile * NKC + c) * ECAP + slot] =
                (unsigned)((q << 13) | (s << 7) | kl);
    }
    __syncthreads();
    if (t < NKC) g_bcnt[tile * NKC + t] = min(scnt[t], ECAP);
}

// ===================== Stage 1b: tiled sampled dots -> M (in-kernel) ========
// Block = (bh, q-tile of 128). Q tile + S scores resident in smem; K streamed
// in double-buffered 128-key chunks with register prefetch (1 sync/chunk).
// Dot arithmetic identical to the round-2/4 passing kernel (8-lane split,
// shuffle tree xor 1,2,4); M finalized in exact s-order -> identical top-k.
__global__ void __launch_bounds__(256) k_gather(const float* __restrict__ Q,
                                                const float* __restrict__ K)
{
    extern __shared__ float smf[];
    float* Qs = smf;                  // QT * PQ
    float* K0 = Qs + QT * PQ;         // KC * PQ
    float* K1 = K0 + KC * PQ;         // KC * PQ
    float* Ss = K1 + KC * PQ;         // QT * SP
    int*  scn = (int*)(Ss + QT * SP); // NKC

    int bx = blockIdx.x;
    int bh = bx >> 4, tile = bx & 15;
    int b = bh >> 3, h = bh & 7;
    int t = threadIdx.x;

    const float* Kb = K + (size_t)b * L * (H * D) + (size_t)h * D;
    const float* Qb = Q + (size_t)b * L * (H * D) + (size_t)h * D
                        + (size_t)tile * QT * (H * D);

    if (t < NKC) scn[t] = g_bcnt[tile * NKC + t];

    // Q tile
    #pragma unroll
    for (int j = 0; j < 8; j++) {
        int i = t + j * 256; int r = i >> 4, col = (i & 15) << 2;
        *(float4*)&Qs[r * PQ + col] = *(const float4*)&Qb[(size_t)r * (H * D) + col];
    }
    // chunk 0 -> K0, prefetch chunk 1 into regs
    float4 pre[8];
    #pragma unroll
    for (int j = 0; j < 8; j++) {
        int i = t + j * 256; int r = i >> 4, col = (i & 15) << 2;
        pre[j] = *(const float4*)&Kb[(size_t)r * (H * D) + col];
    }
    #pragma unroll
    for (int j = 0; j < 8; j++) {
        int i = t + j * 256; int r = i >> 4, col = (i & 15) << 2;
        *(float4*)&K0[r * PQ + col] = pre[j];
    }
    #pragma unroll
    for (int j = 0; j < 8; j++) {
        int i = t + j * 256; int r = i >> 4, col = (i & 15) << 2;
        pre[j] = *(const float4*)&Kb[(size_t)(KC + r) * (H * D) + col];
    }
    __syncthreads();

    int grp = t >> 3, j8 = t & 7;

    for (int c = 0; c < NKC; c++) {
        const float* Kc = (c & 1) ? K1 : K0;
        int cnt = scn[c];
        const unsigned* bk = &g_bkt[(tile * NKC + c) * ECAP];
        for (int it = 0; it * 32 < cnt; it++) {
            int e = it * 32 + grp;
            bool act = e < cnt;
            unsigned pk = act ? bk[e] : 0u;
            int q = pk >> 13, s = (pk >> 7) & 63, kl = pk & 127;
            const float* qp = &Qs[q * PQ + j8 * 8];
            const float* kp = &Kc[kl * PQ + j8 * 8];
            float4 qa = *(const float4*)qp;
            float4 qb = *(const float4*)(qp + 4);
            float4 ka = *(const float4*)kp;
            float4 kb = *(const float4*)(kp + 4);
            float d = qa.x * ka.x + qa.y * ka.y + qa.z * ka.z + qa.w * ka.w
                    + qb.x * kb.x + qb.y * kb.y + qb.z * kb.z + qb.w * kb.w;
            d += __shfl_xor_sync(0xffffffffu, d, 1);
            d += __shfl_xor_sync(0xffffffffu, d, 2);
            d += __shfl_xor_sync(0xffffffffu, d, 4);
            if (act && j8 == 0) Ss[q * SP + s] = d;
        }
        // store prefetched chunk c+1 (buffer last read at chunk c-1 -> safe)
        if (c + 1 < NKC) {
            float* Kn = ((c + 1) & 1) ? K1 : K0;
            #pragma unroll
            for (int j = 0; j < 8; j++) {
                int i = t + j * 256; int r = i >> 4, col = (i & 15) << 2;
                *(float4*)&Kn[r * PQ + col] = pre[j];
            }
        }
        // prefetch chunk c+2
        if (c + 2 < NKC) {
            #pragma unroll
            for (int j = 0; j < 8; j++) {
                int i = t + j * 256; int r = i >> 4, col = (i & 15) << 2;
                pre[j] = *(const float4*)&Kb[(size_t)((c + 2) * KC + r) * (H * D) + col];
            }
        }
        __syncthreads();
    }

    // finalize M in exact s-order (SP=41 -> conflict-free)
    if (t < QT) {
        float mx = -1e30f, sm = 0.f;
        #pragma unroll
        for (int s = 0; s < SK; s++) {
            float v = Ss[t * SP + s];
            mx = fmaxf(mx, v);
            sm += v;
        }
        g_M[bh * L + tile * QT + t] = mx - sm * (1.0f / SK);
    }
}

// ===================== Stage 2: top-U per (b,h) =====================
__global__ void __launch_bounds__(1024) k_topk()
{
    __shared__ float sv[L];
    __shared__ float wv[32];
    __shared__ int   wi[32];
    int bh = blockIdx.x;
    int t = threadIdx.x;
    int w = t >> 5, lane = t & 31;

    sv[t] = g_M[bh * L + t];
    sv[t + 1024] = g_M[bh * L + t + 1024];
    __syncthreads();

    for (int r = 0; r < U; r++) {
        float v0 = sv[t], v1 = sv[t + 1024];
        float bv; int bi;
        if (v0 >= v1) { bv = v0; bi = t; }
        else          { bv = v1; bi = t + 1024; }
        #pragma unroll
        for (int o = 16; o; o >>= 1) {
            float v2 = __shfl_xor_sync(0xffffffffu, bv, o);
            int   i2 = __shfl_xor_sync(0xffffffffu, bi, o);
            if (v2 > bv || (v2 == bv && i2 < bi)) { bv = v2; bi = i2; }
        }
        if (lane == 0) { wv[w] = bv; wi[w] = bi; }
        __syncthreads();
        if (w == 0) {
            bv = wv[lane]; bi = wi[lane];
            #pragma unroll
            for (int o = 16; o; o >>= 1) {
                float v2 = __shfl_xor_sync(0xffffffffu, bv, o);
                int   i2 = __shfl_xor_sync(0xffffffffu, bi, o);
                if (v2 > bv || (v2 == bv && i2 < bi)) { bv = v2; bi = i2; }
            }
            if (lane == 0) {
                g_Mtop[bh * U + r] = bi;
                sv[bi] = -1e38f;
            }
        }
        __syncthreads();
    }
}

// ===================== Stage 3: cumsum of V along L -> out =====================
__global__ void k_cumsum_a(const float* __restrict__ V)
{
    int blk = blockIdx.x;
    int b = blk / NCH, ch = blk % NCH;
    int c = threadIdx.x;
    const float* base = V + ((size_t)b * L + ch * CHUNK) * C + c;
    float s = 0.f;
    #pragma unroll
    for (int l = 0; l < CHUNK; l++) s += base[(size_t)l * C];
    g_csum[((size_t)b * NCH + ch) * C + c] = s;
}

__global__ void k_cumsum_c(const float* __restrict__ V, float* __restrict__ out)
{
    int blk = blockIdx.x;
    int b = blk / NCH, ch = blk % NCH;
    int c = threadIdx.x;
    float run = 0.f;
    for (int j = 0; j < ch; j++)
        run += g_csum[((size_t)b * NCH + j) * C + c];
    const float* vb = V   + ((size_t)b * L + ch * CHUNK) * C + c;
    float*       ob = out + ((size_t)b * L + ch * CHUNK) * C + c;
    #pragma unroll
    for (int l0 = 0; l0 < CHUNK; l0 += 8) {
        float v[8];
        #pragma unroll
        for (int j = 0; j < 8; j++) v[j] = vb[(size_t)(l0 + j) * C];
        #pragma unroll
        for (int j = 0; j < 8; j++) {
            run += v[j];
            ob[(size_t)(l0 + j) * C] = run;
        }
    }
}

// ===================== Stage 4: dense attention partials =====================
__global__ void __launch_bounds__(256) k_attn_partial(
    const float* __restrict__ Q,
    const float* __restrict__ K,
    const float* __restrict__ V)
{
    extern __shared__ float smf[];
    float* Ks = smf;
    float* Vs = Ks + KCH * PKS;
    float* Qs = Vs + KCH * PVS;
    float* pb = Qs + U * D;
    int*   ps = (int*)(pb + 8 * 5 * KCH);

    int bh = blockIdx.x >> 4;
    int ch = blockIdx.x & 15;
    int b = bh >> 3, h = bh & 7;
    int t = threadIdx.x;
    int k0 = ch * KCH;

    for (int i = t; i < KCH * D; i += 256) {
        int r = i >> 6, d = i & 63;
        size_t gidx = (((size_t)b * L + (k0 + r)) * H + h) * D + d;
        Ks[r * PKS + d] = K[gidx];
        Vs[r * PVS + d] = V[gidx];
    }
    if (t < U) ps[t] = g_Mtop[bh * U + t];
    __syncthreads();
    for (int i = t; i < U * D; i += 256) {
        int u = i >> 6, d = i & 63;
        Qs[i] = Q[(((size_t)b * L + ps[u]) * H + h) * D + d];
    }
    __syncthreads();

    int w = t >> 5, lane = t & 31;
    const float4* Qb = (const float4*)Qs;

    float s4[5][4];
    #pragma unroll
    for (int q = 0; q < 5; q++)
        #pragma unroll
        for (int g = 0; g < 4; g++) s4[q][g] = 0.f;

    #pragma unroll 4
    for (int i = 0; i < 16; i++) {
        float4 kk[4];
        #pragma unroll
        for (int g = 0; g < 4; g++)
            kk[g] = *(const float4*)&Ks[(g * 32 + lane) * PKS + 4 * i];
        #pragma unroll
        for (int q = 0; q < 5; q++) {
            float4 qv = Qb[(w * 5 + q) * 16 + i];
            #pragma unroll
            for (int g = 0; g < 4; g++)
                s4[q][g] += qv.x * kk[g].x + qv.y * kk[g].y
                          + qv.z * kk[g].z + qv.w * kk[g].w;
        }
    }

    #pragma unroll
    for (int q = 0; q < 5; q++) {
        int u = w * 5 + q;
        int p = ps[u];
        float sc[4]; bool ok[4];
        float m = -1e30f;
        #pragma unroll
        for (int g = 0; g < 4; g++) {
            sc[g] = s4[q][g] * 0.125f;
            ok[g] = (k0 + g * 32 + lane) <= p;
            m = fmaxf(m, ok[g] ? sc[g] : -1e30f);
        }
        #pragma unroll
        for (int o = 16; o; o >>= 1)
            m = fmaxf(m, __shfl_xor_sync(0xffffffffu, m, o));
        float l = 0.f;
        #pragma unroll
        for (int g = 0; g < 4; g++) {
            float pv = ok[g] ? __expf(sc[g] - m) : 0.f;
            l += pv;
            pb[w * (5 * KCH) + q * KCH + g * 32 + lane] = pv;
        }
        #pragma unroll
        for (int o = 16; o; o >>= 1)
            l += __shfl_xor_sync(0xffffffffu, l, o);
        if (lane == 0) {
            int pi = (bh * U + u) * NCHK + ch;
            g_pm[pi] = m;
            g_pl[pi] = l;
        }
    }
    __syncwarp();

    float2 acc[5];
    #pragma unroll
    for (int q = 0; q < 5; q++) acc[q] = make_float2(0.f, 0.f);

    #pragma unroll 4
    for (int k = 0; k < KCH; k += 4) {
        float2 v0 = *(const float2*)&Vs[(k + 0) * PVS + 2 * lane];
        float2 v1 = *(const float2*)&Vs[(k + 1) * PVS + 2 * lane];
        float2 v2 = *(const float2*)&Vs[(k + 2) * PVS + 2 * lane];
        float2 v3 = *(const float2*)&Vs[(k + 3) * PVS + 2 * lane];
        #pragma unroll
        for (int q = 0; q < 5; q++) {
            float4 pq = *(const float4*)&pb[w * (5 * KCH) + q * KCH + k];
            acc[q].x += pq.x * v0.x + pq.y * v1.x + pq.z * v2.x + pq.w * v3.x;
            acc[q].y += pq.x * v0.y + pq.y * v1.y + pq.z * v2.y + pq.w * v3.y;
        }
    }

    #pragma unroll
    for (int q = 0; q < 5; q++) {
        int u = w * 5 + q;
        int pi = (bh * U + u) * NCHK + ch;
        *(float2*)&g_pacc[(size_t)pi * D + 2 * lane] = acc[q];
    }
}

// ===================== Stage 5: combine partials, scatter rows =====================
__global__ void k_attn_reduce(float* __restrict__ out)
{
    int task = blockIdx.x * (blockDim.x >> 5) + (threadIdx.x >> 5);
    if (task >= BH * U) return;
    int lane = threadIdx.x & 31;
    int bh = task / U, u = task % U;
    int b = bh >> 3, h = bh & 7;

    float m = -1e30f;
    #pragma unroll
    for (int c = 0; c < NCHK; c++) m = fmaxf(m, g_pm[task * NCHK + c]);
    float Lsum = 0.f;
    float2 a = make_float2(0.f, 0.f);
    #pragma unroll
    for (int c = 0; c < NCHK; c++) {
        float wgt = __expf(g_pm[task * NCHK + c] - m);
        Lsum += g_pl[task * NCHK + c] * wgt;
        float2 pa = *(const float2*)&g_pacc[(size_t)(task * NCHK + c) * D + 2 * lane];
        a.x += pa.x * wgt;
        a.y += pa.y * wgt;
    }
    float inv = 1.0f / Lsum;
    int p = g_Mtop[bh * U + u];
    size_t o = (((size_t)b * L + p) * H + h) * D + 2 * lane;
    out[o + 0] = a.x * inv;
    out[o + 1] = a.y * inv;
}

// ===================== launch =====================
extern "C" void kernel_launch(void* const* d_in, const int* in_sizes, int n_in,
                              void* d_out, int out_size)
{
    const float* Q   = (const float*)d_in[0];
    const float* K   = (const float*)d_in[1];
    const float* V   = (const float*)d_in[2];
    const int*   idx = (const int*)d_in[3];
    float* out = (float*)d_out;

    const int smem_g = (QT * PQ + 2 * KC * PQ + QT * SP) * (int)sizeof(float)
                     + NKC * (int)sizeof(int);
    const int smem_a = (KCH * PKS + KCH * PVS + U * D + 8 * 5 * KCH) * (int)sizeof(float)
                     + U * (int)sizeof(int);
    cudaFuncSetAttribute(k_gather, cudaFuncAttributeMaxDynamicSharedMemorySize, smem_g);
    cudaFuncSetAttribute(k_attn_partial, cudaFuncAttributeMaxDynamicSharedMemorySize, smem_a);

    // Stage 1: buckets -> tiled sampled dots -> M (in-kernel)
    k_bucket<<<NQT, 256>>>(idx);
    k_gather<<<BH * NQT, 256, smem_g>>>(Q, K);
    // Stage 2: top-k
    k_topk<<<BH, 1024>>>();
    // Stage 3: cumsum -> out
    k_cumsum_a<<<B * NCH, C>>>(V);
    k_cumsum_c<<<B * NCH, C>>>(V, out);
    // Stage 4: dense attention partials for top queries
    k_attn_partial<<<BH * NCHK, 256, smem_a>>>(Q, K, V);
    // Stage 5: combine + scatter
    k_attn_reduce<<<(BH * U) / 8, 256>>>(out);
}

// round 6
// speedup vs baseline: 2.3831x; 2.3831x over previous
#include <cuda_runtime.h>
#include <cstdint>

// Shapes (fixed by the benchmark)
#define B 4
#define L 2048
#define H 8
#define D 64
#define SK 40          // sample_k
#define U 40           // top-k queries kept
#define BH (B*H)       // 32
#define C (H*D)        // 512 columns for cumsum view

// Attention chunking
#define KCH 128        // keys per chunk in dense attention
#define NCHK (L/KCH)   // 16
#define PKS 68         // Ks pitch (floats): conflict-free float4 key-major reads
#define PVS 66         // Vs pitch (floats): conflict-free float2 d-major reads

// Cumsum chunking
#define NCH 128
#define CHUNK (L/NCH)  // 16

// -------- scratch (device globals; no allocation allowed) --------
__device__ float g_M[BH * L];
__device__ int   g_Mtop[BH * U];
__device__ float g_pm[BH * U * NCHK];
__device__ float g_pl[BH * U * NCHK];
__device__ float g_pacc[BH * U * NCHK * D];
__device__ float g_csum[B * NCH * C];

// ===================== Stage 1: sampled scores -> M =====================
// Block per query q (2048 blocks, 256 threads). Thread t: b=t>>6, h=(t>>3)&7,
// dim-group g=t&7 (8 floats). Q row cached in registers; each sample is one
// fully coalesced 2KB gather of K[b, ki, :, :]; 8-lane butterfly reduce.
// Samples processed in batches of 4: 8 LDG.128 issued before any reduction.
__global__ void __launch_bounds__(256) k_sample_scores(
    const float* __restrict__ Q,
    const float* __restrict__ K,
    const int*   __restrict__ idx)
{
    __shared__ int sidx[SK];
    int q = blockIdx.x;
    int t = threadIdx.x;
    int b = t >> 6;
    int h = (t >> 3) & 7;
    int g = t & 7;

    if (t < SK) sidx[t] = idx[q * SK + t];
    __syncthreads();

    const float* qp = Q + (((size_t)b * L + q) * H + h) * D + g * 8;
    float4 qa = *(const float4*)qp;
    float4 qb = *(const float4*)(qp + 4);

    float mx = -1e30f, sm = 0.f;
    const size_t hoff = (size_t)h * D + (size_t)g * 8;
    const float* Kb = K + (size_t)b * L * (H * D) + hoff;

    #pragma unroll
    for (int s0 = 0; s0 < SK; s0 += 4) {
        float4 ka[4], kb[4];
        #pragma unroll
        for (int j = 0; j < 4; j++) {
            const float* kp = Kb + (size_t)sidx[s0 + j] * (H * D);
            ka[j] = *(const float4*)kp;
            kb[j] = *(const float4*)(kp + 4);
        }
        #pragma unroll
        for (int j = 0; j < 4; j++) {
            float d = qa.x * ka[j].x + qa.y * ka[j].y + qa.z * ka[j].z + qa.w * ka[j].w
                    + qb.x * kb[j].x + qb.y * kb[j].y + qb.z * kb[j].z + qb.w * kb[j].w;
            d += __shfl_xor_sync(0xffffffffu, d, 1);
            d += __shfl_xor_sync(0xffffffffu, d, 2);
            d += __shfl_xor_sync(0xffffffffu, d, 4);
            mx = fmaxf(mx, d);
            sm += d;
        }
    }
    if (g == 0)
        g_M[(t >> 3) * L + q] = mx - sm * (1.0f / SK);
}

// ===================== Stage 2: top-U per (b,h) =====================
// 1024 threads, 2 elems each; shuffle-only argmax per round.
// Ties -> lowest index (matches jax.lax.top_k).
__global__ void __launch_bounds__(1024) k_topk()
{
    __shared__ float sv[L];
    __shared__ float wv[32];
    __shared__ int   wi[32];
    int bh = blockIdx.x;
    int t = threadIdx.x;
    int w = t >> 5, lane = t & 31;

    sv[t] = g_M[bh * L + t];
    sv[t + 1024] = g_M[bh * L + t + 1024];
    __syncthreads();

    for (int r = 0; r < U; r++) {
        float v0 = sv[t], v1 = sv[t + 1024];
        float bv; int bi;
        if (v0 >= v1) { bv = v0; bi = t; }           // tie -> lower index
        else          { bv = v1; bi = t + 1024; }
        #pragma unroll
        for (int o = 16; o; o >>= 1) {
            float v2 = __shfl_xor_sync(0xffffffffu, bv, o);
            int   i2 = __shfl_xor_sync(0xffffffffu, bi, o);
            if (v2 > bv || (v2 == bv && i2 < bi)) { bv = v2; bi = i2; }
        }
        if (lane == 0) { wv[w] = bv; wi[w] = bi; }
        __syncthreads();
        if (w == 0) {
            bv = wv[lane]; bi = wi[lane];
            #pragma unroll
            for (int o = 16; o; o >>= 1) {
                float v2 = __shfl_xor_sync(0xffffffffu, bv, o);
                int   i2 = __shfl_xor_sync(0xffffffffu, bi, o);
                if (v2 > bv || (v2 == bv && i2 < bi)) { bv = v2; bi = i2; }
            }
            if (lane == 0) {
                g_Mtop[bh * U + r] = bi;
                sv[bi] = -1e38f;
            }
        }
        __syncthreads();
    }
}

// ===================== Stage 3: cumsum of V along L -> out =====================
// View V/out as [B][L][C], C = 512. Pass A: chunk sums. Pass C: each block
// computes its own prefix from the (L2-resident) chunk sums, then scans.
__global__ void k_cumsum_a(const float* __restrict__ V)
{
    int blk = blockIdx.x;          // 0 .. B*NCH-1
    int b = blk / NCH, ch = blk % NCH;
    int c = threadIdx.x;           // 512
    const float* base = V + ((size_t)b * L + ch * CHUNK) * C + c;
    float s = 0.f;
    #pragma unroll
    for (int l = 0; l < CHUNK; l++) s += base[(size_t)l * C];
    g_csum[((size_t)b * NCH + ch) * C + c] = s;
}

__global__ void k_cumsum_c(const float* __restrict__ V, float* __restrict__ out)
{
    int blk = blockIdx.x;
    int b = blk / NCH, ch = blk % NCH;
    int c = threadIdx.x;
    float run = 0.f;
    for (int j = 0; j < ch; j++)
        run += g_csum[((size_t)b * NCH + j) * C + c];
    const float* vb = V   + ((size_t)b * L + ch * CHUNK) * C + c;
    float*       ob = out + ((size_t)b * L + ch * CHUNK) * C + c;
    #pragma unroll
    for (int l0 = 0; l0 < CHUNK; l0 += 8) {
        float v[8];
        #pragma unroll
        for (int j = 0; j < 8; j++) v[j] = vb[(size_t)(l0 + j) * C];
        #pragma unroll
        for (int j = 0; j < 8; j++) {
            run += v[j];
            ob[(size_t)(l0 + j) * C] = run;
        }
    }
}

// ===================== Stage 4: dense attention partials =====================
// Block = (b,h, key-chunk). 8 warps; each warp owns 5 of the 40 queries.
__global__ void __launch_bounds__(256) k_attn_partial(
    const float* __restrict__ Q,
    const float* __restrict__ K,
    const float* __restrict__ V)
{
    extern __shared__ float smf[];
    float* Ks = smf;                       // KCH * PKS
    float* Vs = Ks + KCH * PKS;            // KCH * PVS
    float* Qs = Vs + KCH * PVS;            // U * D
    float* pb = Qs + U * D;                // 8 warps * 5 q * 128 k
    int*   ps = (int*)(pb + 8 * 5 * KCH);  // U

    int bh = blockIdx.x >> 4;
    int ch = blockIdx.x & 15;
    int b = bh >> 3, h = bh & 7;
    int t = threadIdx.x;
    int k0 = ch * KCH;

    for (int i = t; i < KCH * D; i += 256) {
        int r = i >> 6, d = i & 63;
        size_t gidx = (((size_t)b * L + (k0 + r)) * H + h) * D + d;
        Ks[r * PKS + d] = K[gidx];
        Vs[r * PVS + d] = V[gidx];
    }
    if (t < U) ps[t] = g_Mtop[bh * U + t];
    __syncthreads();
    for (int i = t; i < U * D; i += 256) {
        int u = i >> 6, d = i & 63;
        Qs[i] = Q[(((size_t)b * L + ps[u]) * H + h) * D + d];
    }
    __syncthreads();

    int w = t >> 5, lane = t & 31;
    const float4* Qb = (const float4*)Qs;

    float s4[5][4];
    #pragma unroll
    for (int q = 0; q < 5; q++)
        #pragma unroll
        for (int g = 0; g < 4; g++) s4[q][g] = 0.f;

    #pragma unroll 4
    for (int i = 0; i < 16; i++) {
        float4 kk[4];
        #pragma unroll
        for (int g = 0; g < 4; g++)
            kk[g] = *(const float4*)&Ks[(g * 32 + lane) * PKS + 4 * i];
        #pragma unroll
        for (int q = 0; q < 5; q++) {
            float4 qv = Qb[(w * 5 + q) * 16 + i];
            #pragma unroll
            for (int g = 0; g < 4; g++)
                s4[q][g] += qv.x * kk[g].x + qv.y * kk[g].y
                          + qv.z * kk[g].z + qv.w * kk[g].w;
        }
    }

    #pragma unroll
    for (int q = 0; q < 5; q++) {
        int u = w * 5 + q;
        int p = ps[u];
        float sc[4]; bool ok[4];
        float m = -1e30f;
        #pragma unroll
        for (int g = 0; g < 4; g++) {
            sc[g] = s4[q][g] * 0.125f;             // 1/sqrt(64)
            ok[g] = (k0 + g * 32 + lane) <= p;
            m = fmaxf(m, ok[g] ? sc[g] : -1e30f);
        }
        #pragma unroll
        for (int o = 16; o; o >>= 1)
            m = fmaxf(m, __shfl_xor_sync(0xffffffffu, m, o));
        float l = 0.f;
        #pragma unroll
        for (int g = 0; g < 4; g++) {
            float pv = ok[g] ? __expf(sc[g] - m) : 0.f;
            l += pv;
            pb[w * (5 * KCH) + q * KCH + g * 32 + lane] = pv;
        }
        #pragma unroll
        for (int o = 16; o; o >>= 1)
            l += __shfl_xor_sync(0xffffffffu, l, o);
        if (lane == 0) {
            int pi = (bh * U + u) * NCHK + ch;
            g_pm[pi] = m;
            g_pl[pi] = l;
        }
    }
    __syncwarp();

    float2 acc[5];
    #pragma unroll
    for (int q = 0; q < 5; q++) acc[q] = make_float2(0.f, 0.f);

    #pragma unroll 4
    for (int k = 0; k < KCH; k += 4) {
        float2 v0 = *(const float2*)&Vs[(k + 0) * PVS + 2 * lane];
        float2 v1 = *(const float2*)&Vs[(k + 1) * PVS + 2 * lane];
        float2 v2 = *(const float2*)&Vs[(k + 2) * PVS + 2 * lane];
        float2 v3 = *(const float2*)&Vs[(k + 3) * PVS + 2 * lane];
        #pragma unroll
        for (int q = 0; q < 5; q++) {
            float4 pq = *(const float4*)&pb[w * (5 * KCH) + q * KCH + k];
            acc[q].x += pq.x * v0.x + pq.y * v1.x + pq.z * v2.x + pq.w * v3.x;
            acc[q].y += pq.x * v0.y + pq.y * v1.y + pq.z * v2.y + pq.w * v3.y;
        }
    }

    #pragma unroll
    for (int q = 0; q < 5; q++) {
        int u = w * 5 + q;
        int pi = (bh * U + u) * NCHK + ch;
        *(float2*)&g_pacc[(size_t)pi * D + 2 * lane] = acc[q];
    }
}

// ===================== Stage 5: combine partials, scatter rows =====================
__global__ void k_attn_reduce(float* __restrict__ out)
{
    int task = blockIdx.x * (blockDim.x >> 5) + (threadIdx.x >> 5);
    if (task >= BH * U) return;
    int lane = threadIdx.x & 31;
    int bh = task / U, u = task % U;
    int b = bh >> 3, h = bh & 7;

    float m = -1e30f;
    #pragma unroll
    for (int c = 0; c < NCHK; c++) m = fmaxf(m, g_pm[task * NCHK + c]);
    float Lsum = 0.f;
    float2 a = make_float2(0.f, 0.f);
    #pragma unroll
    for (int c = 0; c < NCHK; c++) {
        float wgt = __expf(g_pm[task * NCHK + c] - m);
        Lsum += g_pl[task * NCHK + c] * wgt;
        float2 pa = *(const float2*)&g_pacc[(size_t)(task * NCHK + c) * D + 2 * lane];
        a.x += pa.x * wgt;
        a.y += pa.y * wgt;
    }
    float inv = 1.0f / Lsum;
    int p = g_Mtop[bh * U + u];
    size_t o = (((size_t)b * L + p) * H + h) * D + 2 * lane;
    out[o + 0] = a.x * inv;
    out[o + 1] = a.y * inv;
}

// ===================== launch =====================
extern "C" void kernel_launch(void* const* d_in, const int* in_sizes, int n_in,
                              void* d_out, int out_size)
{
    const float* Q   = (const float*)d_in[0];
    const float* K   = (const float*)d_in[1];
    const float* V   = (const float*)d_in[2];
    const int*   idx = (const int*)d_in[3];
    float* out = (float*)d_out;

    // One-time host-side resources (no device memory involved).
    static cudaStream_t s2 = nullptr;
    static cudaEvent_t evFork = nullptr, evJoin = nullptr;
    if (!s2) {
        cudaStreamCreateWithFlags(&s2, cudaStreamNonBlocking);
        cudaEventCreateWithFlags(&evFork, cudaEventDisableTiming);
        cudaEventCreateWithFlags(&evJoin, cudaEventDisableTiming);
    }

    const int smem_a = (KCH * PKS + KCH * PVS + U * D + 8 * 5 * KCH) * (int)sizeof(float)
                     + U * (int)sizeof(int);
    cudaFuncSetAttribute(k_attn_partial, cudaFuncAttributeMaxDynamicSharedMemorySize, smem_a);

    // Fork: cumsum chain on side stream (independent of sample/topk/attn).
    cudaEventRecord(evFork, 0);
    cudaStreamWaitEvent(s2, evFork, 0);
    k_cumsum_a<<<B * NCH, C, 0, s2>>>(V);
    k_cumsum_c<<<B * NCH, C, 0, s2>>>(V, out);
    cudaEventRecord(evJoin, s2);

    // Main chain on default stream.
    k_sample_scores<<<L, 256>>>(Q, K, idx);
    k_topk<<<BH, 1024>>>();
    k_attn_partial<<<BH * NCHK, 256, smem_a>>>(Q, K, V);

    // Join: reduce overwrites the selected rows of out written by cumsum_c.
    cudaStreamWaitEvent(0, evJoin, 0);
    k_attn_reduce<<<(BH * U) / 8, 256>>>(out);
}

// round 7
// speedup vs baseline: 2.5071x; 1.0520x over previous
#include <cuda_runtime.h>
#include <cstdint>

// Shapes (fixed by the benchmark)
#define B 4
#define L 2048
#define H 8
#define D 64
#define SK 40          // sample_k
#define U 40           // top-k queries kept
#define BH (B*H)       // 32
#define C (H*D)        // 512 columns for cumsum view

// Attention chunking
#define KCH 128        // keys per chunk in dense attention
#define NCHK (L/KCH)   // 16
#define PKS 68         // Ks pitch (floats): conflict-free float4 key-major reads
#define PVS 66         // Vs pitch (floats): conflict-free float2 d-major reads

// Cumsum chunking
#define NCH 128
#define CHUNK (L/NCH)  // 16

// -------- scratch (device globals; no allocation allowed) --------
__device__ float g_M[BH * L];
__device__ int   g_Mtop[BH * U];
__device__ float g_pm[BH * U * NCHK];
__device__ float g_pl[BH * U * NCHK];
__device__ float g_pacc[BH * U * NCHK * D];
__device__ float g_csum[B * NCH * C];

// ===================== Stage 1: sampled scores -> M =====================
// Block per query q (2048 blocks, 256 threads). Thread t: b=t>>6, h=(t>>3)&7,
// dim-group g=t&7 (8 floats). Q row cached in registers; each sample is one
// fully coalesced 2KB gather of K[b, ki, :, :]; 8-lane butterfly reduce.
// Samples processed in batches of 4: 8 LDG.128 issued before any reduction.
__global__ void __launch_bounds__(256) k_sample_scores(
    const float* __restrict__ Q,
    const float* __restrict__ K,
    const int*   __restrict__ idx)
{
    __shared__ int sidx[SK];
    int q = blockIdx.x;
    int t = threadIdx.x;
    int b = t >> 6;
    int h = (t >> 3) & 7;
    int g = t & 7;

    if (t < SK) sidx[t] = idx[q * SK + t];
    __syncthreads();

    const float* qp = Q + (((size_t)b * L + q) * H + h) * D + g * 8;
    float4 qa = *(const float4*)qp;
    float4 qb = *(const float4*)(qp + 4);

    float mx = -1e30f, sm = 0.f;
    const size_t hoff = (size_t)h * D + (size_t)g * 8;
    const float* Kb = K + (size_t)b * L * (H * D) + hoff;

    #pragma unroll
    for (int s0 = 0; s0 < SK; s0 += 4) {
        float4 ka[4], kb[4];
        #pragma unroll
        for (int j = 0; j < 4; j++) {
            const float* kp = Kb + (size_t)sidx[s0 + j] * (H * D);
            ka[j] = *(const float4*)kp;
            kb[j] = *(const float4*)(kp + 4);
        }
        #pragma unroll
        for (int j = 0; j < 4; j++) {
            float d = qa.x * ka[j].x + qa.y * ka[j].y + qa.z * ka[j].z + qa.w * ka[j].w
                    + qb.x * kb[j].x + qb.y * kb[j].y + qb.z * kb[j].z + qb.w * kb[j].w;
            d += __shfl_xor_sync(0xffffffffu, d, 1);
            d += __shfl_xor_sync(0xffffffffu, d, 2);
            d += __shfl_xor_sync(0xffffffffu, d, 4);
            mx = fmaxf(mx, d);
            sm += d;
        }
    }
    if (g == 0)
        g_M[(t >> 3) * L + q] = mx - sm * (1.0f / SK);
}

// ===================== Stage 2: exact top-U via radix select =====================
// Order-preserving float->u32 map; 4x 8-bit MSB->LSB histogram passes find the
// exact 40th-largest key K and rem = #(==K) to keep. Emit all keys > K plus the
// rem lowest-indexed keys == K (jax.lax.top_k tie semantics). Output order is a
// set; downstream consumers are order-invariant.
__device__ __forceinline__ unsigned f2ord(float f)
{
    unsigned u = __float_as_uint(f);
    return (u & 0x80000000u) ? ~u : (u | 0x80000000u);
}

#define EQCAP 256

__global__ void __launch_bounds__(1024) k_topk()
{
    __shared__ unsigned keys[L];
    __shared__ int hist[256];
    __shared__ unsigned s_prefix;
    __shared__ int s_rem, s_cnt, s_eqcnt;
    __shared__ int eqidx[EQCAP];

    int bh = blockIdx.x;
    int t = threadIdx.x;

    keys[t]        = f2ord(g_M[bh * L + t]);
    keys[t + 1024] = f2ord(g_M[bh * L + t + 1024]);
    if (t == 0) { s_prefix = 0u; s_rem = U; }
    __syncthreads();

    unsigned mask = 0u;
    #pragma unroll
    for (int shift = 24; shift >= 0; shift -= 8) {
        if (t < 256) hist[t] = 0;
        __syncthreads();
        unsigned pre = s_prefix;
        #pragma unroll
        for (int j = 0; j < 2; j++) {
            unsigned k = keys[t + j * 1024];
            if ((k & mask) == pre)
                atomicAdd(&hist[(k >> shift) & 255], 1);
        }
        __syncthreads();
        if (t == 0) {
            int c = 0, bin = 255;
            for (; bin > 0; bin--) {
                if (c + hist[bin] >= s_rem) break;
                c += hist[bin];
            }
            s_rem -= c;
            s_prefix = pre | ((unsigned)bin << shift);
        }
        mask |= (0xFFu << shift);
        __syncthreads();
    }

    if (t == 0) { s_cnt = 0; s_eqcnt = 0; }
    __syncthreads();
    unsigned Kthr = s_prefix;
    #pragma unroll
    for (int j = 0; j < 2; j++) {
        int i = t + j * 1024;
        unsigned k = keys[i];
        if (k > Kthr) {
            int p = atomicAdd(&s_cnt, 1);
            g_Mtop[bh * U + p] = i;
        } else if (k == Kthr) {
            int p = atomicAdd(&s_eqcnt, 1);
            if (p < EQCAP) eqidx[p] = i;
        }
    }
    __syncthreads();
    if (t == 0) {
        int n = min(s_eqcnt, EQCAP);
        int base = s_cnt;            // == U - s_rem by construction
        for (int r = 0; r < s_rem; r++) {
            int best = 1 << 30, bj = 0;
            for (int j = 0; j < n; j++)
                if (eqidx[j] < best) { best = eqidx[j]; bj = j; }
            g_Mtop[bh * U + base + r] = best;
            eqidx[bj] = 1 << 30;
        }
    }
}

// ===================== Stage 3: cumsum of V along L -> out =====================
__global__ void k_cumsum_a(const float* __restrict__ V)
{
    int blk = blockIdx.x;
    int b = blk / NCH, ch = blk % NCH;
    int c = threadIdx.x;
    const float* base = V + ((size_t)b * L + ch * CHUNK) * C + c;
    float s = 0.f;
    #pragma unroll
    for (int l = 0; l < CHUNK; l++) s += base[(size_t)l * C];
    g_csum[((size_t)b * NCH + ch) * C + c] = s;
}

__global__ void k_cumsum_c(const float* __restrict__ V, float* __restrict__ out)
{
    int blk = blockIdx.x;
    int b = blk / NCH, ch = blk % NCH;
    int c = threadIdx.x;
    float run = 0.f;
    for (int j = 0; j < ch; j++)
        run += g_csum[((size_t)b * NCH + j) * C + c];
    const float* vb = V   + ((size_t)b * L + ch * CHUNK) * C + c;
    float*       ob = out + ((size_t)b * L + ch * CHUNK) * C + c;
    #pragma unroll
    for (int l0 = 0; l0 < CHUNK; l0 += 8) {
        float v[8];
        #pragma unroll
        for (int j = 0; j < 8; j++) v[j] = vb[(size_t)(l0 + j) * C];
        #pragma unroll
        for (int j = 0; j < 8; j++) {
            run += v[j];
            ob[(size_t)(l0 + j) * C] = run;
        }
    }
}

// ===================== Stage 4: dense attention partials =====================
__global__ void __launch_bounds__(256) k_attn_partial(
    const float* __restrict__ Q,
    const float* __restrict__ K,
    const float* __restrict__ V)
{
    extern __shared__ float smf[];
    float* Ks = smf;                       // KCH * PKS
    float* Vs = Ks + KCH * PKS;            // KCH * PVS
    float* Qs = Vs + KCH * PVS;            // U * D
    float* pb = Qs + U * D;                // 8 warps * 5 q * 128 k
    int*   ps = (int*)(pb + 8 * 5 * KCH);  // U

    int bh = blockIdx.x >> 4;
    int ch = blockIdx.x & 15;
    int b = bh >> 3, h = bh & 7;
    int t = threadIdx.x;
    int k0 = ch * KCH;

    for (int i = t; i < KCH * D; i += 256) {
        int r = i >> 6, d = i & 63;
        size_t gidx = (((size_t)b * L + (k0 + r)) * H + h) * D + d;
        Ks[r * PKS + d] = K[gidx];
        Vs[r * PVS + d] = V[gidx];
    }
    if (t < U) ps[t] = g_Mtop[bh * U + t];
    __syncthreads();
    for (int i = t; i < U * D; i += 256) {
        int u = i >> 6, d = i & 63;
        Qs[i] = Q[(((size_t)b * L + ps[u]) * H + h) * D + d];
    }
    __syncthreads();

    int w = t >> 5, lane = t & 31;
    const float4* Qb = (const float4*)Qs;

    float s4[5][4];
    #pragma unroll
    for (int q = 0; q < 5; q++)
        #pragma unroll
        for (int g = 0; g < 4; g++) s4[q][g] = 0.f;

    #pragma unroll 4
    for (int i = 0; i < 16; i++) {
        float4 kk[4];
        #pragma unroll
        for (int g = 0; g < 4; g++)
            kk[g] = *(const float4*)&Ks[(g * 32 + lane) * PKS + 4 * i];
        #pragma unroll
        for (int q = 0; q < 5; q++) {
            float4 qv = Qb[(w * 5 + q) * 16 + i];
            #pragma unroll
            for (int g = 0; g < 4; g++)
                s4[q][g] += qv.x * kk[g].x + qv.y * kk[g].y
                          + qv.z * kk[g].z + qv.w * kk[g].w;
        }
    }

    #pragma unroll
    for (int q = 0; q < 5; q++) {
        int u = w * 5 + q;
        int p = ps[u];
        float sc[4]; bool ok[4];
        float m = -1e30f;
        #pragma unroll
        for (int g = 0; g < 4; g++) {
            sc[g] = s4[q][g] * 0.125f;             // 1/sqrt(64)
            ok[g] = (k0 + g * 32 + lane) <= p;
            m = fmaxf(m, ok[g] ? sc[g] : -1e30f);
        }
        #pragma unroll
        for (int o = 16; o; o >>= 1)
            m = fmaxf(m, __shfl_xor_sync(0xffffffffu, m, o));
        float l = 0.f;
        #pragma unroll
        for (int g = 0; g < 4; g++) {
            float pv = ok[g] ? __expf(sc[g] - m) : 0.f;
            l += pv;
            pb[w * (5 * KCH) + q * KCH + g * 32 + lane] = pv;
        }
        #pragma unroll
        for (int o = 16; o; o >>= 1)
            l += __shfl_xor_sync(0xffffffffu, l, o);
        if (lane == 0) {
            int pi = (bh * U + u) * NCHK + ch;
            g_pm[pi] = m;
            g_pl[pi] = l;
        }
    }
    __syncwarp();

    float2 acc[5];
    #pragma unroll
    for (int q = 0; q < 5; q++) acc[q] = make_float2(0.f, 0.f);

    #pragma unroll 4
    for (int k = 0; k < KCH; k += 4) {
        float2 v0 = *(const float2*)&Vs[(k + 0) * PVS + 2 * lane];
        float2 v1 = *(const float2*)&Vs[(k + 1) * PVS + 2 * lane];
        float2 v2 = *(const float2*)&Vs[(k + 2) * PVS + 2 * lane];
        float2 v3 = *(const float2*)&Vs[(k + 3) * PVS + 2 * lane];
        #pragma unroll
        for (int q = 0; q < 5; q++) {
            float4 pq = *(const float4*)&pb[w * (5 * KCH) + q * KCH + k];
            acc[q].x += pq.x * v0.x + pq.y * v1.x + pq.z * v2.x + pq.w * v3.x;
            acc[q].y += pq.x * v0.y + pq.y * v1.y + pq.z * v2.y + pq.w * v3.y;
        }
    }

    #pragma unroll
    for (int q = 0; q < 5; q++) {
        int u = w * 5 + q;
        int pi = (bh * U + u) * NCHK + ch;
        *(float2*)&g_pacc[(size_t)pi * D + 2 * lane] = acc[q];
    }
}

// ===================== Stage 5: combine partials, scatter rows =====================
__global__ void k_attn_reduce(float* __restrict__ out)
{
    int task = blockIdx.x * (blockDim.x >> 5) + (threadIdx.x >> 5);
    if (task >= BH * U) return;
    int lane = threadIdx.x & 31;
    int bh = task / U, u = task % U;
    int b = bh >> 3, h = bh & 7;

    float m = -1e30f;
    #pragma unroll
    for (int c = 0; c < NCHK; c++) m = fmaxf(m, g_pm[task * NCHK + c]);
    float Lsum = 0.f;
    float2 a = make_float2(0.f, 0.f);
    #pragma unroll
    for (int c = 0; c < NCHK; c++) {
        float wgt = __expf(g_pm[task * NCHK + c] - m);
        Lsum += g_pl[task * NCHK + c] * wgt;
        float2 pa = *(const float2*)&g_pacc[(size_t)(task * NCHK + c) * D + 2 * lane];
        a.x += pa.x * wgt;
        a.y += pa.y * wgt;
    }
    float inv = 1.0f / Lsum;
    int p = g_Mtop[bh * U + u];
    size_t o = (((size_t)b * L + p) * H + h) * D + 2 * lane;
    out[o + 0] = a.x * inv;
    out[o + 1] = a.y * inv;
}

// ===================== launch =====================
extern "C" void kernel_launch(void* const* d_in, const int* in_sizes, int n_in,
                              void* d_out, int out_size)
{
    const float* Q   = (const float*)d_in[0];
    const float* K   = (const float*)d_in[1];
    const float* V   = (const float*)d_in[2];
    const int*   idx = (const int*)d_in[3];
    float* out = (float*)d_out;

    // One-time host-side resources (no device memory involved).
    static cudaStream_t s2 = nullptr;
    static cudaEvent_t evFork = nullptr, evJoin = nullptr;
    if (!s2) {
        cudaStreamCreateWithFlags(&s2, cudaStreamNonBlocking);
        cudaEventCreateWithFlags(&evFork, cudaEventDisableTiming);
        cudaEventCreateWithFlags(&evJoin, cudaEventDisableTiming);
    }

    const int smem_a = (KCH * PKS + KCH * PVS + U * D + 8 * 5 * KCH) * (int)sizeof(float)
                     + U * (int)sizeof(int);
    cudaFuncSetAttribute(k_attn_partial, cudaFuncAttributeMaxDynamicSharedMemorySize, smem_a);

    // Fork: cumsum chain on side stream (independent of sample/topk/attn).
    cudaEventRecord(evFork, 0);
    cudaStreamWaitEvent(s2, evFork, 0);
    k_cumsum_a<<<B * NCH, C, 0, s2>>>(V);
    k_cumsum_c<<<B * NCH, C, 0, s2>>>(V, out);
    cudaEventRecord(evJoin, s2);

    // Main chain on default stream.
    k_sample_scores<<<L, 256>>>(Q, K, idx);
    k_topk<<<BH, 1024>>>();
    k_attn_partial<<<BH * NCHK, 256, smem_a>>>(Q, K, V);

    // Join: reduce overwrites the selected rows of out written by cumsum_c.
    cudaStreamWaitEvent(0, evJoin, 0);
    k_attn_reduce<<<(BH * U) / 8, 256>>>(out);
}

// round 8
// speedup vs baseline: 2.6017x; 1.0377x over previous
#include <cuda_runtime.h>
#include <cstdint>

// Shapes (fixed by the benchmark)
#define B 4
#define L 2048
#define H 8
#define D 64
#define SK 40          // sample_k
#define U 40           // top-k queries kept
#define BH (B*H)       // 32
#define C (H*D)        // 512 columns for cumsum view

// Attention chunking
#define KCH 128        // keys per chunk in dense attention
#define NCHK (L/KCH)   // 16
#define PKS 68         // Ks pitch (floats): conflict-free float4 key-major reads
#define PVS 66         // Vs pitch (floats): conflict-free float2 d-major reads

// Cumsum chunking
#define NCH 128
#define CHUNK (L/NCH)  // 16

// -------- scratch (device globals; no allocation allowed) --------
__device__ float g_M[BH * L];
__device__ int   g_Mtop[BH * U];
__device__ float g_pm[BH * U * NCHK];
__device__ float g_pl[BH * U * NCHK];
__device__ float g_pacc[BH * U * NCHK * D];
__device__ float g_csum[B * NCH * C];

// ===================== Stage 1: sampled scores -> M =====================
// Block per query q (2048 blocks, 256 threads). Thread t: b=t>>6, h=(t>>3)&7,
// dim-group g=t&7 (8 floats). Q row cached in registers; each sample is one
// fully coalesced 2KB gather of K[b, ki, :, :]; 8-lane butterfly reduce.
// Samples processed in batches of 4: 8 LDG.128 issued before any reduction.
__global__ void __launch_bounds__(256) k_sample_scores(
    const float* __restrict__ Q,
    const float* __restrict__ K,
    const int*   __restrict__ idx)
{
    __shared__ int sidx[SK];
    int q = blockIdx.x;
    int t = threadIdx.x;
    int b = t >> 6;
    int h = (t >> 3) & 7;
    int g = t & 7;

    if (t < SK) sidx[t] = idx[q * SK + t];
    __syncthreads();

    const float* qp = Q + (((size_t)b * L + q) * H + h) * D + g * 8;
    float4 qa = *(const float4*)qp;
    float4 qb = *(const float4*)(qp + 4);

    float mx = -1e30f, sm = 0.f;
    const size_t hoff = (size_t)h * D + (size_t)g * 8;
    const float* Kb = K + (size_t)b * L * (H * D) + hoff;

    #pragma unroll
    for (int s0 = 0; s0 < SK; s0 += 4) {
        float4 ka[4], kb[4];
        #pragma unroll
        for (int j = 0; j < 4; j++) {
            const float* kp = Kb + (size_t)sidx[s0 + j] * (H * D);
            ka[j] = *(const float4*)kp;
            kb[j] = *(const float4*)(kp + 4);
        }
        #pragma unroll
        for (int j = 0; j < 4; j++) {
            float d = qa.x * ka[j].x + qa.y * ka[j].y + qa.z * ka[j].z + qa.w * ka[j].w
                    + qb.x * kb[j].x + qb.y * kb[j].y + qb.z * kb[j].z + qb.w * kb[j].w;
            d += __shfl_xor_sync(0xffffffffu, d, 1);
            d += __shfl_xor_sync(0xffffffffu, d, 2);
            d += __shfl_xor_sync(0xffffffffu, d, 4);
            mx = fmaxf(mx, d);
            sm += d;
        }
    }
    if (g == 0)
        g_M[(t >> 3) * L + q] = mx - sm * (1.0f / SK);
}

// ===================== Stage 2: exact top-U via radix select =====================
// Order-preserving float->u32 map; 4x 8-bit MSB->LSB histogram passes find the
// exact 40th-largest key K and rem = #(==K) to keep. Threshold bin found with a
// 256-wide parallel suffix-count scan (the serial 256-bin walk was a ~30K-cycle
// dependent-LDS chain and dominated the old kernel). Emit all keys > K plus the
// rem lowest-indexed keys == K (jax.lax.top_k tie semantics; order irrelevant).
__device__ __forceinline__ unsigned f2ord(float f)
{
    unsigned u = __float_as_uint(f);
    return (u & 0x80000000u) ? ~u : (u | 0x80000000u);
}

#define EQCAP 256

__global__ void __launch_bounds__(1024) k_topk()
{
    __shared__ unsigned keys[L];
    __shared__ int hist[256];
    __shared__ int scn[256];
    __shared__ unsigned s_prefix;
    __shared__ int s_rem, s_cnt, s_eqcnt;
    __shared__ int eqidx[EQCAP];

    int bh = blockIdx.x;
    int t = threadIdx.x;

    keys[t]        = f2ord(g_M[bh * L + t]);
    keys[t + 1024] = f2ord(g_M[bh * L + t + 1024]);
    if (t == 0) { s_prefix = 0u; s_rem = U; }
    __syncthreads();

    unsigned mask = 0u;
    #pragma unroll
    for (int shift = 24; shift >= 0; shift -= 8) {
        if (t < 256) hist[t] = 0;
        __syncthreads();
        unsigned pre = s_prefix;
        int rem = s_rem;
        #pragma unroll
        for (int j = 0; j < 2; j++) {
            unsigned k = keys[t + j * 1024];
            if ((k & mask) == pre)
                atomicAdd(&hist[(k >> shift) & 255], 1);
        }
        __syncthreads();
        // scn[i] = count of candidates in bins >= 255-i (inclusive suffix count)
        if (t < 256) scn[t] = hist[255 - t];
        __syncthreads();
        #pragma unroll
        for (int off = 1; off < 256; off <<= 1) {
            int add = (t < 256 && t >= off) ? scn[t - off] : 0;
            __syncthreads();
            if (t < 256) scn[t] += add;
            __syncthreads();
        }
        if (t < 256) {
            int cum = scn[t];
            int prev = t ? scn[t - 1] : 0;
            if (cum >= rem && prev < rem) {       // exactly one thread
                s_prefix = pre | ((unsigned)(255 - t) << shift);
                s_rem = rem - prev;
            }
        }
        mask |= (0xFFu << shift);
        __syncthreads();
    }

    if (t == 0) { s_cnt = 0; s_eqcnt = 0; }
    __syncthreads();
    unsigned Kthr = s_prefix;
    #pragma unroll
    for (int j = 0; j < 2; j++) {
        int i = t + j * 1024;
        unsigned k = keys[i];
        if (k > Kthr) {
            int p = atomicAdd(&s_cnt, 1);
            g_Mtop[bh * U + p] = i;
        } else if (k == Kthr) {
            int p = atomicAdd(&s_eqcnt, 1);
            if (p < EQCAP) eqidx[p] = i;
        }
    }
    __syncthreads();
    if (t == 0) {
        int n = min(s_eqcnt, EQCAP);
        int base = s_cnt;            // == U - s_rem by construction
        for (int r = 0; r < s_rem; r++) {
            int best = 1 << 30, bj = 0;
            for (int j = 0; j < n; j++)
                if (eqidx[j] < best) { best = eqidx[j]; bj = j; }
            g_Mtop[bh * U + base + r] = best;
            eqidx[bj] = 1 << 30;
        }
    }
}

// ===================== Stage 3: cumsum of V along L -> out =====================
__global__ void k_cumsum_a(const float* __restrict__ V)
{
    int blk = blockIdx.x;
    int b = blk / NCH, ch = blk % NCH;
    int c = threadIdx.x;
    const float* base = V + ((size_t)b * L + ch * CHUNK) * C + c;
    float s = 0.f;
    #pragma unroll
    for (int l = 0; l < CHUNK; l++) s += base[(size_t)l * C];
    g_csum[((size_t)b * NCH + ch) * C + c] = s;
}

__global__ void k_cumsum_c(const float* __restrict__ V, float* __restrict__ out)
{
    int blk = blockIdx.x;
    int b = blk / NCH, ch = blk % NCH;
    int c = threadIdx.x;
    float run = 0.f;
    for (int j = 0; j < ch; j++)
        run += g_csum[((size_t)b * NCH + j) * C + c];
    const float* vb = V   + ((size_t)b * L + ch * CHUNK) * C + c;
    float*       ob = out + ((size_t)b * L + ch * CHUNK) * C + c;
    #pragma unroll
    for (int l0 = 0; l0 < CHUNK; l0 += 8) {
        float v[8];
        #pragma unroll
        for (int j = 0; j < 8; j++) v[j] = vb[(size_t)(l0 + j) * C];
        #pragma unroll
        for (int j = 0; j < 8; j++) {
            run += v[j];
            ob[(size_t)(l0 + j) * C] = run;
        }
    }
}

// ===================== Stage 4: dense attention partials =====================
__global__ void __launch_bounds__(256) k_attn_partial(
    const float* __restrict__ Q,
    const float* __restrict__ K,
    const float* __restrict__ V)
{
    extern __shared__ float smf[];
    float* Ks = smf;                       // KCH * PKS
    float* Vs = Ks + KCH * PKS;            // KCH * PVS
    float* Qs = Vs + KCH * PVS;            // U * D
    float* pb = Qs + U * D;                // 8 warps * 5 q * 128 k
    int*   ps = (int*)(pb + 8 * 5 * KCH);  // U

    int bh = blockIdx.x >> 4;
    int ch = blockIdx.x & 15;
    int b = bh >> 3, h = bh & 7;
    int t = threadIdx.x;
    int k0 = ch * KCH;

    for (int i = t; i < KCH * D; i += 256) {
        int r = i >> 6, d = i & 63;
        size_t gidx = (((size_t)b * L + (k0 + r)) * H + h) * D + d;
        Ks[r * PKS + d] = K[gidx];
        Vs[r * PVS + d] = V[gidx];
    }
    if (t < U) ps[t] = g_Mtop[bh * U + t];
    __syncthreads();
    for (int i = t; i < U * D; i += 256) {
        int u = i >> 6, d = i & 63;
        Qs[i] = Q[(((size_t)b * L + ps[u]) * H + h) * D + d];
    }
    __syncthreads();

    int w = t >> 5, lane = t & 31;
    const float4* Qb = (const float4*)Qs;

    float s4[5][4];
    #pragma unroll
    for (int q = 0; q < 5; q++)
        #pragma unroll
        for (int g = 0; g < 4; g++) s4[q][g] = 0.f;

    #pragma unroll 4
    for (int i = 0; i < 16; i++) {
        float4 kk[4];
        #pragma unroll
        for (int g = 0; g < 4; g++)
            kk[g] = *(const float4*)&Ks[(g * 32 + lane) * PKS + 4 * i];
        #pragma unroll
        for (int q = 0; q < 5; q++) {
            float4 qv = Qb[(w * 5 + q) * 16 + i];
            #pragma unroll
            for (int g = 0; g < 4; g++)
                s4[q][g] += qv.x * kk[g].x + qv.y * kk[g].y
                          + qv.z * kk[g].z + qv.w * kk[g].w;
        }
    }

    #pragma unroll
    for (int q = 0; q < 5; q++) {
        int u = w * 5 + q;
        int p = ps[u];
        float sc[4]; bool ok[4];
        float m = -1e30f;
        #pragma unroll
        for (int g = 0; g < 4; g++) {
            sc[g] = s4[q][g] * 0.125f;             // 1/sqrt(64)
            ok[g] = (k0 + g * 32 + lane) <= p;
            m = fmaxf(m, ok[g] ? sc[g] : -1e30f);
        }
        #pragma unroll
        for (int o = 16; o; o >>= 1)
            m = fmaxf(m, __shfl_xor_sync(0xffffffffu, m, o));
        float l = 0.f;
        #pragma unroll
        for (int g = 0; g < 4; g++) {
            float pv = ok[g] ? __expf(sc[g] - m) : 0.f;
            l += pv;
            pb[w * (5 * KCH) + q * KCH + g * 32 + lane] = pv;
        }
        #pragma unroll
        for (int o = 16; o; o >>= 1)
            l += __shfl_xor_sync(0xffffffffu, l, o);
        if (lane == 0) {
            int pi = (bh * U + u) * NCHK + ch;
            g_pm[pi] = m;
            g_pl[pi] = l;
        }
    }
    __syncwarp();

    float2 acc[5];
    #pragma unroll
    for (int q = 0; q < 5; q++) acc[q] = make_float2(0.f, 0.f);

    #pragma unroll 4
    for (int k = 0; k < KCH; k += 4) {
        float2 v0 = *(const float2*)&Vs[(k + 0) * PVS + 2 * lane];
        float2 v1 = *(const float2*)&Vs[(k + 1) * PVS + 2 * lane];
        float2 v2 = *(const float2*)&Vs[(k + 2) * PVS + 2 * lane];
        float2 v3 = *(const float2*)&Vs[(k + 3) * PVS + 2 * lane];
        #pragma unroll
        for (int q = 0; q < 5; q++) {
            float4 pq = *(const float4*)&pb[w * (5 * KCH) + q * KCH + k];
            acc[q].x += pq.x * v0.x + pq.y * v1.x + pq.z * v2.x + pq.w * v3.x;
            acc[q].y += pq.x * v0.y + pq.y * v1.y + pq.z * v2.y + pq.w * v3.y;
        }
    }

    #pragma unroll
    for (int q = 0; q < 5; q++) {
        int u = w * 5 + q;
        int pi = (bh * U + u) * NCHK + ch;
        *(float2*)&g_pacc[(size_t)pi * D + 2 * lane] = acc[q];
    }
}

// ===================== Stage 5: combine partials, scatter rows =====================
__global__ void k_attn_reduce(float* __restrict__ out)
{
    int task = blockIdx.x * (blockDim.x >> 5) + (threadIdx.x >> 5);
    if (task >= BH * U) return;
    int lane = threadIdx.x & 31;
    int bh = task / U, u = task % U;
    int b = bh >> 3, h = bh & 7;

    float m = -1e30f;
    #pragma unroll
    for (int c = 0; c < NCHK; c++) m = fmaxf(m, g_pm[task * NCHK + c]);
    float Lsum = 0.f;
    float2 a = make_float2(0.f, 0.f);
    #pragma unroll
    for (int c = 0; c < NCHK; c++) {
        float wgt = __expf(g_pm[task * NCHK + c] - m);
        Lsum += g_pl[task * NCHK + c] * wgt;
        float2 pa = *(const float2*)&g_pacc[(size_t)(task * NCHK + c) * D + 2 * lane];
        a.x += pa.x * wgt;
        a.y += pa.y * wgt;
    }
    float inv = 1.0f / Lsum;
    int p = g_Mtop[bh * U + u];
    size_t o = (((size_t)b * L + p) * H + h) * D + 2 * lane;
    out[o + 0] = a.x * inv;
    out[o + 1] = a.y * inv;
}

// ===================== launch =====================
extern "C" void kernel_launch(void* const* d_in, const int* in_sizes, int n_in,
                              void* d_out, int out_size)
{
    const float* Q   = (const float*)d_in[0];
    const float* K   = (const float*)d_in[1];
    const float* V   = (const float*)d_in[2];
    const int*   idx = (const int*)d_in[3];
    float* out = (float*)d_out;

    // One-time host-side resources (no device memory involved).
    static cudaStream_t s2 = nullptr;
    static cudaEvent_t evFork = nullptr, evJoin = nullptr;
    if (!s2) {
        cudaStreamCreateWithFlags(&s2, cudaStreamNonBlocking);
        cudaEventCreateWithFlags(&evFork, cudaEventDisableTiming);
        cudaEventCreateWithFlags(&evJoin, cudaEventDisableTiming);
    }

    const int smem_a = (KCH * PKS + KCH * PVS + U * D + 8 * 5 * KCH) * (int)sizeof(float)
                     + U * (int)sizeof(int);
    cudaFuncSetAttribute(k_attn_partial, cudaFuncAttributeMaxDynamicSharedMemorySize, smem_a);

    // Fork: cumsum chain on side stream (independent of sample/topk/attn).
    cudaEventRecord(evFork, 0);
    cudaStreamWaitEvent(s2, evFork, 0);
    k_cumsum_a<<<B * NCH, C, 0, s2>>>(V);
    k_cumsum_c<<<B * NCH, C, 0, s2>>>(V, out);
    cudaEventRecord(evJoin, s2);

    // Main chain on default stream.
    k_sample_scores<<<L, 256>>>(Q, K, idx);
    k_topk<<<BH, 1024>>>();
    k_attn_partial<<<BH * NCHK, 256, smem_a>>>(Q, K, V);

    // Join: reduce overwrites the selected rows of out written by cumsum_c.
    cudaStreamWaitEvent(0, evJoin, 0);
    k_attn_reduce<<<(BH * U) / 8, 256>>>(out);
}

// round 9
// speedup vs baseline: 2.8922x; 1.1116x over previous
#include <cuda_runtime.h>
#include <cstdint>

// Shapes (fixed by the benchmark)
#define B 4
#define L 2048
#define H 8
#define D 64
#define SK 40          // sample_k
#define U 40           // top-k queries kept
#define BH (B*H)       // 32
#define C (H*D)        // 512 columns for cumsum view

// Attention chunking
#define KCH 128        // keys per chunk in dense attention
#define NCHK (L/KCH)   // 16
#define PKS 68         // Ks pitch (floats): conflict-free float4 key-major reads
#define PVS 66         // Vs pitch (floats): conflict-free float2 d-major reads

// Cumsum chunking
#define NCH 128
#define CHUNK (L/NCH)  // 16

// -------- scratch (device globals; no allocation allowed) --------
__device__ float g_M[BH * L];
__device__ int   g_Mtop[BH * U];
__device__ float g_pm[BH * U * NCHK];
__device__ float g_pl[BH * U * NCHK];
__device__ float g_pacc[BH * U * NCHK * D];
__device__ float g_csum[B * NCH * C];

// ===================== Stage 1: sampled scores -> M =====================
__global__ void __launch_bounds__(256) k_sample_scores(
    const float* __restrict__ Q,
    const float* __restrict__ K,
    const int*   __restrict__ idx)
{
    __shared__ int sidx[SK];
    int q = blockIdx.x;
    int t = threadIdx.x;
    int b = t >> 6;
    int h = (t >> 3) & 7;
    int g = t & 7;

    if (t < SK) sidx[t] = idx[q * SK + t];
    __syncthreads();

    const float* qp = Q + (((size_t)b * L + q) * H + h) * D + g * 8;
    float4 qa = *(const float4*)qp;
    float4 qb = *(const float4*)(qp + 4);

    float mx = -1e30f, sm = 0.f;
    const size_t hoff = (size_t)h * D + (size_t)g * 8;
    const float* Kb = K + (size_t)b * L * (H * D) + hoff;

    #pragma unroll
    for (int s0 = 0; s0 < SK; s0 += 4) {
        float4 ka[4], kb[4];
        #pragma unroll
        for (int j = 0; j < 4; j++) {
            const float* kp = Kb + (size_t)sidx[s0 + j] * (H * D);
            ka[j] = *(const float4*)kp;
            kb[j] = *(const float4*)(kp + 4);
        }
        #pragma unroll
        for (int j = 0; j < 4; j++) {
            float d = qa.x * ka[j].x + qa.y * ka[j].y + qa.z * ka[j].z + qa.w * ka[j].w
                    + qb.x * kb[j].x + qb.y * kb[j].y + qb.z * kb[j].z + qb.w * kb[j].w;
            d += __shfl_xor_sync(0xffffffffu, d, 1);
            d += __shfl_xor_sync(0xffffffffu, d, 2);
            d += __shfl_xor_sync(0xffffffffu, d, 4);
            mx = fmaxf(mx, d);
            sm += d;
        }
    }
    if (g == 0)
        g_M[(t >> 3) * L + q] = mx - sm * (1.0f / SK);
}

// ===================== Stage 2: exact top-U via radix select =====================
// 4x 8-bit MSB->LSB passes; threshold bin located by a SINGLE-WARP suffix scan
// (lane owns 8 descending bins; shfl_up prefix across lanes) -> 2 block barriers
// per pass instead of 16. Ties resolved to lowest index (jax.lax.top_k).
// Final indices are rank-sorted ascending: g_Mtop is consumed as a SET, and
// ascending order gives warps in k_attn_partial adjacent causal horizons.
__device__ __forceinline__ unsigned f2ord(float f)
{
    unsigned u = __float_as_uint(f);
    return (u & 0x80000000u) ? ~u : (u | 0x80000000u);
}

#define EQCAP 256

__global__ void __launch_bounds__(1024) k_topk()
{
    __shared__ unsigned keys[L];
    __shared__ int hist[256];
    __shared__ unsigned s_prefix;
    __shared__ int s_rem, s_cnt, s_eqcnt;
    __shared__ int eqidx[EQCAP];
    __shared__ int tmpi[U];

    int bh = blockIdx.x;
    int t = threadIdx.x;

    keys[t]        = f2ord(g_M[bh * L + t]);
    keys[t + 1024] = f2ord(g_M[bh * L + t + 1024]);
    if (t == 0) { s_prefix = 0u; s_rem = U; }
    __syncthreads();

    unsigned mask = 0u;
    #pragma unroll
    for (int shift = 24; shift >= 0; shift -= 8) {
        if (t < 256) hist[t] = 0;
        __syncthreads();
        unsigned pre = s_prefix;
        #pragma unroll
        for (int j = 0; j < 2; j++) {
            unsigned k = keys[t + j * 1024];
            if ((k & mask) == pre)
                atomicAdd(&hist[(k >> shift) & 255], 1);
        }
        __syncthreads();
        if (t < 32) {
            int rem = s_rem;                      // warp-uniform read before write
            int loc[8], sum = 0;
            #pragma unroll
            for (int j = 0; j < 8; j++) {
                loc[j] = hist[255 - (t * 8 + j)]; // descending bins
                sum += loc[j];
            }
            int pref = sum;
            #pragma unroll
            for (int o = 1; o < 32; o <<= 1) {
                int v = __shfl_up_sync(0xffffffffu, pref, o);
                if (t >= o) pref += v;
            }
            int c = pref - sum;                   // count in bins above this lane's group
            #pragma unroll
            for (int j = 0; j < 8; j++) {
                int nc = c + loc[j];
                if (c < rem && nc >= rem) {       // exactly one (lane,j)
                    s_prefix = pre | ((unsigned)(255 - (t * 8 + j)) << shift);
                    s_rem = rem - c;
                }
                c = nc;
            }
        }
        mask |= (0xFFu << shift);
        __syncthreads();
    }

    if (t == 0) { s_cnt = 0; s_eqcnt = 0; }
    __syncthreads();
    unsigned Kthr = s_prefix;
    #pragma unroll
    for (int j = 0; j < 2; j++) {
        int i = t + j * 1024;
        unsigned k = keys[i];
        if (k > Kthr) {
            int p = atomicAdd(&s_cnt, 1);
            tmpi[p] = i;
        } else if (k == Kthr) {
            int p = atomicAdd(&s_eqcnt, 1);
            if (p < EQCAP) eqidx[p] = i;
        }
    }
    __syncthreads();
    if (t == 0) {
        int n = min(s_eqcnt, EQCAP);
        int base = s_cnt;            // == U - s_rem by construction
        for (int r = 0; r < s_rem; r++) {
            int best = 1 << 30, bj = 0;
            for (int j = 0; j < n; j++)
                if (eqidx[j] < best) { best = eqidx[j]; bj = j; }
            tmpi[base + r] = best;
            eqidx[bj] = 1 << 30;
        }
    }
    __syncthreads();
    // rank-sort ascending (indices distinct); order is free to choose
    if (t < U) {
        int v = tmpi[t], r = 0;
        #pragma unroll
        for (int j = 0; j < U; j++) r += (tmpi[j] < v);
        g_Mtop[bh * U + r] = v;
    }
}

// ===================== Stage 3: cumsum of V along L -> out =====================
__global__ void k_cumsum_a(const float* __restrict__ V)
{
    int blk = blockIdx.x;
    int b = blk / NCH, ch = blk % NCH;
    int c = threadIdx.x;
    const float* base = V + ((size_t)b * L + ch * CHUNK) * C + c;
    float s = 0.f;
    #pragma unroll
    for (int l = 0; l < CHUNK; l++) s += base[(size_t)l * C];
    g_csum[((size_t)b * NCH + ch) * C + c] = s;
}

__global__ void k_cumsum_c(const float* __restrict__ V, float* __restrict__ out)
{
    int blk = blockIdx.x;
    int b = blk / NCH, ch = blk % NCH;
    int c = threadIdx.x;
    float run = 0.f;
    for (int j = 0; j < ch; j++)
        run += g_csum[((size_t)b * NCH + j) * C + c];
    const float* vb = V   + ((size_t)b * L + ch * CHUNK) * C + c;
    float*       ob = out + ((size_t)b * L + ch * CHUNK) * C + c;
    #pragma unroll
    for (int l0 = 0; l0 < CHUNK; l0 += 8) {
        float v[8];
        #pragma unroll
        for (int j = 0; j < 8; j++) v[j] = vb[(size_t)(l0 + j) * C];
        #pragma unroll
        for (int j = 0; j < 8; j++) {
            run += v[j];
            ob[(size_t)(l0 + j) * C] = run;
        }
    }
}

// ===================== Stage 4: dense attention partials =====================
// ps[] is sorted ascending -> warp's 5 queries have adjacent causal horizons.
// If even the warp's max horizon is below this chunk, the whole chunk is masked
// for all 5 queries: emit (m=-1e30, l=0, acc=0) -- bit-identical to the full
// computation on a fully-masked chunk -- and skip score+AV entirely.
__global__ void __launch_bounds__(256) k_attn_partial(
    const float* __restrict__ Q,
    const float* __restrict__ K,
    const float* __restrict__ V)
{
    extern __shared__ float smf[];
    float* Ks = smf;                       // KCH * PKS
    float* Vs = Ks + KCH * PKS;            // KCH * PVS
    float* Qs = Vs + KCH * PVS;            // U * D
    float* pb = Qs + U * D;                // 8 warps * 5 q * 128 k
    int*   ps = (int*)(pb + 8 * 5 * KCH);  // U

    int bh = blockIdx.x >> 4;
    int ch = blockIdx.x & 15;
    int b = bh >> 3, h = bh & 7;
    int t = threadIdx.x;
    int k0 = ch * KCH;

    for (int i = t; i < KCH * D; i += 256) {
        int r = i >> 6, d = i & 63;
        size_t gidx = (((size_t)b * L + (k0 + r)) * H + h) * D + d;
        Ks[r * PKS + d] = K[gidx];
        Vs[r * PVS + d] = V[gidx];
    }
    if (t < U) ps[t] = g_Mtop[bh * U + t];
    __syncthreads();
    for (int i = t; i < U * D; i += 256) {
        int u = i >> 6, d = i & 63;
        Qs[i] = Q[(((size_t)b * L + ps[u]) * H + h) * D + d];
    }
    __syncthreads();

    int w = t >> 5, lane = t & 31;
    const float4* Qb = (const float4*)Qs;

    // whole-warp causal skip (no block barriers after this point)
    if (ps[w * 5 + 4] < k0) {
        #pragma unroll
        for (int q = 0; q < 5; q++) {
            int pi = (bh * U + w * 5 + q) * NCHK + ch;
            if (lane == 0) { g_pm[pi] = -1e30f; g_pl[pi] = 0.f; }
            *(float2*)&g_pacc[(size_t)pi * D + 2 * lane] = make_float2(0.f, 0.f);
        }
        return;
    }

    float s4[5][4];
    #pragma unroll
    for (int q = 0; q < 5; q++)
        #pragma unroll
        for (int g = 0; g < 4; g++) s4[q][g] = 0.f;

    #pragma unroll 4
    for (int i = 0; i < 16; i++) {
        float4 kk[4];
        #pragma unroll
        for (int g = 0; g < 4; g++)
            kk[g] = *(const float4*)&Ks[(g * 32 + lane) * PKS + 4 * i];
        #pragma unroll
        for (int q = 0; q < 5; q++) {
            float4 qv = Qb[(w * 5 + q) * 16 + i];
            #pragma unroll
            for (int g = 0; g < 4; g++)
                s4[q][g] += qv.x * kk[g].x + qv.y * kk[g].y
                          + qv.z * kk[g].z + qv.w * kk[g].w;
        }
    }

    #pragma unroll
    for (int q = 0; q < 5; q++) {
        int u = w * 5 + q;
        int p = ps[u];
        float sc[4]; bool ok[4];
        float m = -1e30f;
        #pragma unroll
        for (int g = 0; g < 4; g++) {
            sc[g] = s4[q][g] * 0.125f;             // 1/sqrt(64)
            ok[g] = (k0 + g * 32 + lane) <= p;
            m = fmaxf(m, ok[g] ? sc[g] : -1e30f);
        }
        #pragma unroll
        for (int o = 16; o; o >>= 1)
            m = fmaxf(m, __shfl_xor_sync(0xffffffffu, m, o));
        float l = 0.f;
        #pragma unroll
        for (int g = 0; g < 4; g++) {
            float pv = ok[g] ? __expf(sc[g] - m) : 0.f;
            l += pv;
            pb[w * (5 * KCH) + q * KCH + g * 32 + lane] = pv;
        }
        #pragma unroll
        for (int o = 16; o; o >>= 1)
            l += __shfl_xor_sync(0xffffffffu, l, o);
        if (lane == 0) {
            int pi = (bh * U + u) * NCHK + ch;
            g_pm[pi] = m;
            g_pl[pi] = l;
        }
    }
    __syncwarp();

    float2 acc[5];
    #pragma unroll
    for (int q = 0; q < 5; q++) acc[q] = make_float2(0.f, 0.f);

    #pragma unroll 4
    for (int k = 0; k < KCH; k += 4) {
        float2 v0 = *(const float2*)&Vs[(k + 0) * PVS + 2 * lane];
        float2 v1 = *(const float2*)&Vs[(k + 1) * PVS + 2 * lane];
        float2 v2 = *(const float2*)&Vs[(k + 2) * PVS + 2 * lane];
        float2 v3 = *(const float2*)&Vs[(k + 3) * PVS + 2 * lane];
        #pragma unroll
        for (int q = 0; q < 5; q++) {
            float4 pq = *(const float4*)&pb[w * (5 * KCH) + q * KCH + k];
            acc[q].x += pq.x * v0.x + pq.y * v1.x + pq.z * v2.x + pq.w * v3.x;
            acc[q].y += pq.x * v0.y + pq.y * v1.y + pq.z * v2.y + pq.w * v3.y;
        }
    }

    #pragma unroll
    for (int q = 0; q < 5; q++) {
        int u = w * 5 + q;
        int pi = (bh * U + u) * NCHK + ch;
        *(float2*)&g_pacc[(size_t)pi * D + 2 * lane] = acc[q];
    }
}

// ===================== Stage 5: combine partials, scatter rows =====================
__global__ void k_attn_reduce(float* __restrict__ out)
{
    int task = blockIdx.x * (blockDim.x >> 5) + (threadIdx.x >> 5);
    if (task >= BH * U) return;
    int lane = threadIdx.x & 31;
    int bh = task / U, u = task % U;
    int b = bh >> 3, h = bh & 7;

    float m = -1e30f;
    #pragma unroll
    for (int c = 0; c < NCHK; c++) m = fmaxf(m, g_pm[task * NCHK + c]);
    float Lsum = 0.f;
    float2 a = make_float2(0.f, 0.f);
    #pragma unroll
    for (int c = 0; c < NCHK; c++) {
        float wgt = __expf(g_pm[task * NCHK + c] - m);
        Lsum += g_pl[task * NCHK + c] * wgt;
        float2 pa = *(const float2*)&g_pacc[(size_t)(task * NCHK + c) * D + 2 * lane];
        a.x += pa.x * wgt;
        a.y += pa.y * wgt;
    }
    float inv = 1.0f / Lsum;
    int p = g_Mtop[bh * U + u];
    size_t o = (((size_t)b * L + p) * H + h) * D + 2 * lane;
    out[o + 0] = a.x * inv;
    out[o + 1] = a.y * inv;
}

// ===================== launch =====================
extern "C" void kernel_launch(void* const* d_in, const int* in_sizes, int n_in,
                              void* d_out, int out_size)
{
    const float* Q   = (const float*)d_in[0];
    const float* K   = (const float*)d_in[1];
    const float* V   = (const float*)d_in[2];
    const int*   idx = (const int*)d_in[3];
    float* out = (float*)d_out;

    // One-time host-side resources (no device memory involved).
    static cudaStream_t s2 = nullptr;
    static cudaEvent_t evFork = nullptr, evJoin = nullptr;
    if (!s2) {
        cudaStreamCreateWithFlags(&s2, cudaStreamNonBlocking);
        cudaEventCreateWithFlags(&evFork, cudaEventDisableTiming);
        cudaEventCreateWithFlags(&evJoin, cudaEventDisableTiming);
    }

    const int smem_a = (KCH * PKS + KCH * PVS + U * D + 8 * 5 * KCH) * (int)sizeof(float)
                     + U * (int)sizeof(int);
    cudaFuncSetAttribute(k_attn_partial, cudaFuncAttributeMaxDynamicSharedMemorySize, smem_a);

    // Fork: cumsum chain on side stream (independent of sample/topk/attn).
    cudaEventRecord(evFork, 0);
    cudaStreamWaitEvent(s2, evFork, 0);
    k_cumsum_a<<<B * NCH, C, 0, s2>>>(V);
    k_cumsum_c<<<B * NCH, C, 0, s2>>>(V, out);
    cudaEventRecord(evJoin, s2);

    // Main chain on default stream.
    k_sample_scores<<<L, 256>>>(Q, K, idx);
    k_topk<<<BH, 1024>>>();
    k_attn_partial<<<BH * NCHK, 256, smem_a>>>(Q, K, V);

    // Join: reduce overwrites the selected rows of out written by cumsum_c.
    cudaStreamWaitEvent(0, evJoin, 0);
    k_attn_reduce<<<(BH * U) / 8, 256>>>(out);
}

// round 11
// speedup vs baseline: 3.0518x; 1.0552x over previous
#include <cuda_runtime.h>
#include <cstdint>

// Shapes (fixed by the benchmark)
#define B 4
#define L 2048
#define H 8
#define D 64
#define SK 40          // sample_k
#define U 40           // top-k queries kept
#define BH (B*H)       // 32
#define C (H*D)        // 512 columns for cumsum view

// Attention chunking
#define KCH 128        // keys per chunk in dense attention
#define NCHK (L/KCH)   // 16
#define PKS 68         // Ks pitch (floats): conflict-free float4 key-major reads
#define PVS 66         // Vs pitch (floats): conflict-free float2 d-major reads

// Cumsum chunking
#define NCH 128
#define CHUNK (L/NCH)  // 16

// -------- scratch (device globals; no allocation allowed) --------
__device__ float g_M[BH * L];
__device__ int   g_Mtop[BH * U];
__device__ float g_pm[BH * U * NCHK];
__device__ float g_pl[BH * U * NCHK];
__device__ float g_pacc[BH * U * NCHK * D];
__device__ float g_csum[B * NCH * C];

// ===================== Stage 1: sampled scores -> M =====================
// Block per query q. Thread t = (b=t>>6, h=(t>>3)&7, g=t&7); thread owns dims
// [8g, 8g+8). Samples processed in batches of 8: 16 independent LDG.128, 8
// partial dots, then a 3-stage butterfly REDUCE-SCATTER (7 shuffles per 8
// samples vs 24 for per-sample all-reduce). Lane g ends with the complete dot
// of sample 8*bi+g; the addition tree per sample is bit-identical to the
// xor-1/2/4 butterfly of the previous passing kernel.
__global__ void __launch_bounds__(256) k_sample_scores(
    const float* __restrict__ Q,
    const float* __restrict__ K,
    const int*   __restrict__ idx)
{
    __shared__ int sidx[SK];
    int q = blockIdx.x;
    int t = threadIdx.x;
    int b = t >> 6;
    int h = (t >> 3) & 7;
    int g = t & 7;

    if (t < SK) sidx[t] = idx[q * SK + t];
    __syncthreads();

    const float* qp = Q + (((size_t)b * L + q) * H + h) * D + g * 8;
    float4 qa = *(const float4*)qp;
    float4 qb = *(const float4*)(qp + 4);

    const size_t hoff = (size_t)h * D + (size_t)g * 8;
    const float* Kb = K + (size_t)b * L * (H * D) + hoff;

    const int b0 = g & 1, b1 = (g >> 1) & 1, b2 = (g >> 2) & 1;

    float mx = -1e30f, sm = 0.f;

    for (int bi = 0; bi < 5; bi++) {
        float4 ka[8], kc[8];
        #pragma unroll
        for (int k = 0; k < 8; k++) {
            const float* kp = Kb + (size_t)sidx[bi * 8 + k] * (H * D);
            ka[k] = *(const float4*)kp;
            kc[k] = *(const float4*)(kp + 4);
        }
        float p[8];
        #pragma unroll
        for (int k = 0; k < 8; k++)
            p[k] = qa.x * ka[k].x + qa.y * ka[k].y + qa.z * ka[k].z + qa.w * ka[k].w
                 + qb.x * kc[k].x + qb.y * kc[k].y + qb.z * kc[k].z + qb.w * kc[k].w;

        // stage 1 (xor 1): keep samples with bit0 == b0
        float q4[4];
        #pragma unroll
        for (int j = 0; j < 4; j++) {
            float keep = b0 ? p[2 * j + 1] : p[2 * j];
            float send = b0 ? p[2 * j]     : p[2 * j + 1];
            q4[j] = keep + __shfl_xor_sync(0xffffffffu, send, 1);
        }
        // stage 2 (xor 2): keep samples with bit1 == b1
        float r2[2];
        #pragma unroll
        for (int j = 0; j < 2; j++) {
            float keep = b1 ? q4[2 * j + 1] : q4[2 * j];
            float send = b1 ? q4[2 * j]     : q4[2 * j + 1];
            r2[j] = keep + __shfl_xor_sync(0xffffffffu, send, 2);
        }
        // stage 3 (xor 4): keep sample with bit2 == b2
        float keep = b2 ? r2[1] : r2[0];
        float send = b2 ? r2[0] : r2[1];
        float d = keep + __shfl_xor_sync(0xffffffffu, send, 4);

        // d = full 64-dim dot of sample bi*8 + g
        mx = fmaxf(mx, d);
        sm += d;
    }

    // combine max/sum across the 8 threads sharing (b,h)
    #pragma unroll
    for (int o = 1; o < 8; o <<= 1) {
        mx = fmaxf(mx, __shfl_xor_sync(0xffffffffu, mx, o));
        sm += __shfl_xor_sync(0xffffffffu, sm, o);
    }
    if (g == 0)
        g_M[(t >> 3) * L + q] = mx - sm * (1.0f / SK);
}

// ===================== Stage 2: exact top-U via radix select =====================
__device__ __forceinline__ unsigned f2ord(float f)
{
    unsigned u = __float_as_uint(f);
    return (u & 0x80000000u) ? ~u : (u | 0x80000000u);
}

#define EQCAP 256

__global__ void __launch_bounds__(1024) k_topk()
{
    __shared__ unsigned keys[L];
    __shared__ int hist[256];
    __shared__ unsigned s_prefix;
    __shared__ int s_rem, s_cnt, s_eqcnt;
    __shared__ int eqidx[EQCAP];
    __shared__ int tmpi[U];

    int bh = blockIdx.x;
    int t = threadIdx.x;

    keys[t]        = f2ord(g_M[bh * L + t]);
    keys[t + 1024] = f2ord(g_M[bh * L + t + 1024]);
    if (t == 0) { s_prefix = 0u; s_rem = U; }
    __syncthreads();

    unsigned mask = 0u;
    #pragma unroll
    for (int shift = 24; shift >= 0; shift -= 8) {
        if (t < 256) hist[t] = 0;
        __syncthreads();
        unsigned pre = s_prefix;
        #pragma unroll
        for (int j = 0; j < 2; j++) {
            unsigned k = keys[t + j * 1024];
            if ((k & mask) == pre)
                atomicAdd(&hist[(k >> shift) & 255], 1);
        }
        __syncthreads();
        if (t < 32) {
            int rem = s_rem;
            int loc[8], sum = 0;
            #pragma unroll
            for (int j = 0; j < 8; j++) {
                loc[j] = hist[255 - (t * 8 + j)];
                sum += loc[j];
            }
            int pref = sum;
            #pragma unroll
            for (int o = 1; o < 32; o <<= 1) {
                int v = __shfl_up_sync(0xffffffffu, pref, o);
                if (t >= o) pref += v;
            }
            int c = pref - sum;
            #pragma unroll
            for (int j = 0; j < 8; j++) {
                int nc = c + loc[j];
                if (c < rem && nc >= rem) {
                    s_prefix = pre | ((unsigned)(255 - (t * 8 + j)) << shift);
                    s_rem = rem - c;
                }
                c = nc;
            }
        }
        mask |= (0xFFu << shift);
        __syncthreads();
    }

    if (t == 0) { s_cnt = 0; s_eqcnt = 0; }
    __syncthreads();
    unsigned Kthr = s_prefix;
    #pragma unroll
    for (int j = 0; j < 2; j++) {
        int i = t + j * 1024;
        unsigned k = keys[i];
        if (k > Kthr) {
            int p = atomicAdd(&s_cnt, 1);
            tmpi[p] = i;
        } else if (k == Kthr) {
            int p = atomicAdd(&s_eqcnt, 1);
            if (p < EQCAP) eqidx[p] = i;
        }
    }
    __syncthreads();
    if (t == 0) {
        int n = min(s_eqcnt, EQCAP);
        int base = s_cnt;
        for (int r = 0; r < s_rem; r++) {
            int best = 1 << 30, bj = 0;
            for (int j = 0; j < n; j++)
                if (eqidx[j] < best) { best = eqidx[j]; bj = j; }
            tmpi[base + r] = best;
            eqidx[bj] = 1 << 30;
        }
    }
    __syncthreads();
    if (t < U) {
        int v = tmpi[t], r = 0;
        #pragma unroll
        for (int j = 0; j < U; j++) r += (tmpi[j] < v);
        g_Mtop[bh * U + r] = v;
    }
}

// ===================== Stage 3: cumsum of V along L -> out =====================
__global__ void k_cumsum_a(const float* __restrict__ V)
{
    int blk = blockIdx.x;
    int b = blk / NCH, ch = blk % NCH;
    int c = threadIdx.x;
    const float* base = V + ((size_t)b * L + ch * CHUNK) * C + c;
    float s = 0.f;
    #pragma unroll
    for (int l = 0; l < CHUNK; l++) s += base[(size_t)l * C];
    g_csum[((size_t)b * NCH + ch) * C + c] = s;
}

__global__ void k_cumsum_c(const float* __restrict__ V, float* __restrict__ out)
{
    int blk = blockIdx.x;
    int b = blk / NCH, ch = blk % NCH;
    int c = threadIdx.x;
    float run = 0.f;
    for (int j = 0; j < ch; j++)
        run += g_csum[((size_t)b * NCH + j) * C + c];
    const float* vb = V   + ((size_t)b * L + ch * CHUNK) * C + c;
    float*       ob = out + ((size_t)b * L + ch * CHUNK) * C + c;
    #pragma unroll
    for (int l0 = 0; l0 < CHUNK; l0 += 8) {
        float v[8];
        #pragma unroll
        for (int j = 0; j < 8; j++) v[j] = vb[(size_t)(l0 + j) * C];
        #pragma unroll
        for (int j = 0; j < 8; j++) {
            run += v[j];
            ob[(size_t)(l0 + j) * C] = run;
        }
    }
}

// ===================== Stage 4: dense attention partials =====================
__global__ void __launch_bounds__(256) k_attn_partial(
    const float* __restrict__ Q,
    const float* __restrict__ K,
    const float* __restrict__ V)
{
    extern __shared__ float smf[];
    float* Ks = smf;                       // KCH * PKS
    float* Vs = Ks + KCH * PKS;            // KCH * PVS
    float* Qs = Vs + KCH * PVS;            // U * D
    float* pb = Qs + U * D;                // 8 warps * 5 q * 128 k
    int*   ps = (int*)(pb + 8 * 5 * KCH);  // U

    int bh = blockIdx.x >> 4;
    int ch = blockIdx.x & 15;
    int b = bh >> 3, h = bh & 7;
    int t = threadIdx.x;
    int k0 = ch * KCH;

    for (int i = t; i < KCH * D; i += 256) {
        int r = i >> 6, d = i & 63;
        size_t gidx = (((size_t)b * L + (k0 + r)) * H + h) * D + d;
        Ks[r * PKS + d] = K[gidx];
        Vs[r * PVS + d] = V[gidx];
    }
    if (t < U) ps[t] = g_Mtop[bh * U + t];
    __syncthreads();
    for (int i = t; i < U * D; i += 256) {
        int u = i >> 6, d = i & 63;
        Qs[i] = Q[(((size_t)b * L + ps[u]) * H + h) * D + d];
    }
    __syncthreads();

    int w = t >> 5, lane = t & 31;
    const float4* Qb = (const float4*)Qs;

    // whole-warp causal skip (ps sorted ascending; no block barriers below)
    if (ps[w * 5 + 4] < k0) {
        #pragma unroll
        for (int q = 0; q < 5; q++) {
            int pi = (bh * U + w * 5 + q) * NCHK + ch;
            if (lane == 0) { g_pm[pi] = -1e30f; g_pl[pi] = 0.f; }
            *(float2*)&g_pacc[(size_t)pi * D + 2 * lane] = make_float2(0.f, 0.f);
        }
        return;
    }

    float s4[5][4];
    #pragma unroll
    for (int q = 0; q < 5; q++)
        #pragma unroll
        for (int g = 0; g < 4; g++) s4[q][g] = 0.f;

    #pragma unroll 4
    for (int i = 0; i < 16; i++) {
        float4 kk[4];
        #pragma unroll
        for (int g = 0; g < 4; g++)
            kk[g] = *(const float4*)&Ks[(g * 32 + lane) * PKS + 4 * i];
        #pragma unroll
        for (int q = 0; q < 5; q++) {
            float4 qv = Qb[(w * 5 + q) * 16 + i];
            #pragma unroll
            for (int g = 0; g < 4; g++)
                s4[q][g] += qv.x * kk[g].x + qv.y * kk[g].y
                          + qv.z * kk[g].z + qv.w * kk[g].w;
        }
    }

    #pragma unroll
    for (int q = 0; q < 5; q++) {
        int u = w * 5 + q;
        int p = ps[u];
        float sc[4]; bool ok[4];
        float m = -1e30f;
        #pragma unroll
        for (int g = 0; g < 4; g++) {
            sc[g] = s4[q][g] * 0.125f;             // 1/sqrt(64)
            ok[g] = (k0 + g * 32 + lane) <= p;
            m = fmaxf(m, ok[g] ? sc[g] : -1e30f);
        }
        #pragma unroll
        for (int o = 16; o; o >>= 1)
            m = fmaxf(m, __shfl_xor_sync(0xffffffffu, m, o));
        float l = 0.f;
        #pragma unroll
        for (int g = 0; g < 4; g++) {
            float pv = ok[g] ? __expf(sc[g] - m) : 0.f;
            l += pv;
            pb[w * (5 * KCH) + q * KCH + g * 32 + lane] = pv;
        }
        #pragma unroll
        for (int o = 16; o; o >>= 1)
            l += __shfl_xor_sync(0xffffffffu, l, o);
        if (lane == 0) {
            int pi = (bh * U + u) * NCHK + ch;
            g_pm[pi] = m;
            g_pl[pi] = l;
        }
    }
    __syncwarp();

    float2 acc[5];
    #pragma unroll
    for (int q = 0; q < 5; q++) acc[q] = make_float2(0.f, 0.f);

    #pragma unroll 4
    for (int k = 0; k < KCH; k += 4) {
        float2 v0 = *(const float2*)&Vs[(k + 0) * PVS + 2 * lane];
        float2 v1 = *(const float2*)&Vs[(k + 1) * PVS + 2 * lane];
        float2 v2 = *(const float2*)&Vs[(k + 2) * PVS + 2 * lane];
        float2 v3 = *(const float2*)&Vs[(k + 3) * PVS + 2 * lane];
        #pragma unroll
        for (int q = 0; q < 5; q++) {
            float4 pq = *(const float4*)&pb[w * (5 * KCH) + q * KCH + k];
            acc[q].x += pq.x * v0.x + pq.y * v1.x + pq.z * v2.x + pq.w * v3.x;
            acc[q].y += pq.x * v0.y + pq.y * v1.y + pq.z * v2.y + pq.w * v3.y;
        }
    }

    #pragma unroll
    for (int q = 0; q < 5; q++) {
        int u = w * 5 + q;
        int pi = (bh * U + u) * NCHK + ch;
        *(float2*)&g_pacc[(size_t)pi * D + 2 * lane] = acc[q];
    }
}

// ===================== Stage 5: combine partials, scatter rows =====================
__global__ void k_attn_reduce(float* __restrict__ out)
{
    int task = blockIdx.x * (blockDim.x >> 5) + (threadIdx.x >> 5);
    if (task >= BH * U) return;
    int lane = threadIdx.x & 31;
    int bh = task / U, u = task % U;
    int b = bh >> 3, h = bh & 7;

    float m = -1e30f;
    #pragma unroll
    for (int c = 0; c < NCHK; c++) m = fmaxf(m, g_pm[task * NCHK + c]);
    float Lsum = 0.f;
    float2 a = make_float2(0.f, 0.f);
    #pragma unroll
    for (int c = 0; c < NCHK; c++) {
        float wgt = __expf(g_pm[task * NCHK + c] - m);
        Lsum += g_pl[task * NCHK + c] * wgt;
        float2 pa = *(const float2*)&g_pacc[(size_t)(task * NCHK + c) * D + 2 * lane];
        a.x += pa.x * wgt;
        a.y += pa.y * wgt;
    }
    float inv = 1.0f / Lsum;
    int p = g_Mtop[bh * U + u];
    size_t o = (((size_t)b * L + p) * H + h) * D + 2 * lane;
    out[o + 0] = a.x * inv;
    out[o + 1] = a.y * inv;
}

// ===================== launch =====================
extern "C" void kernel_launch(void* const* d_in, const int* in_sizes, int n_in,
                              void* d_out, int out_size)
{
    const float* Q   = (const float*)d_in[0];
    const float* K   = (const float*)d_in[1];
    const float* V   = (const float*)d_in[2];
    const int*   idx = (const int*)d_in[3];
    float* out = (float*)d_out;

    // One-time host-side resources (no device memory involved).
    static cudaStream_t s2 = nullptr;
    static cudaEvent_t evFork = nullptr, evJoin = nullptr;
    if (!s2) {
        cudaStreamCreateWithFlags(&s2, cudaStreamNonBlocking);
        cudaEventCreateWithFlags(&evFork, cudaEventDisableTiming);
        cudaEventCreateWithFlags(&evJoin, cudaEventDisableTiming);
    }

    const int smem_a = (KCH * PKS + KCH * PVS + U * D + 8 * 5 * KCH) * (int)sizeof(float)
                     + U * (int)sizeof(int);
    cudaFuncSetAttribute(k_attn_partial, cudaFuncAttributeMaxDynamicSharedMemorySize, smem_a);

    // Fork: cumsum chain on side stream (independent of sample/topk/attn).
    cudaEventRecord(evFork, 0);
    cudaStreamWaitEvent(s2, evFork, 0);
    k_cumsum_a<<<B * NCH, C, 0, s2>>>(V);
    k_cumsum_c<<<B * NCH, C, 0, s2>>>(V, out);
    cudaEventRecord(evJoin, s2);

    // Main chain on default stream.
    k_sample_scores<<<L, 256>>>(Q, K, idx);
    k_topk<<<BH, 1024>>>();
    k_attn_partial<<<BH * NCHK, 256, smem_a>>>(Q, K, V);

    // Join: reduce overwrites the selected rows of out written by cumsum_c.
    cudaStreamWaitEvent(0, evJoin, 0);
    k_attn_reduce<<<(BH * U) / 8, 256>>>(out);
}

// round 13
// speedup vs baseline: 3.1089x; 1.0187x over previous
#include <cuda_runtime.h>
#include <cstdint>

// Shapes (fixed by the benchmark)
#define B 4
#define L 2048
#define H 8
#define D 64
#define SK 40          // sample_k
#define U 40           // top-k queries kept
#define BH (B*H)       // 32
#define C (H*D)        // 512 columns for cumsum view

// Attention chunking
#define KCH 128        // keys per chunk in dense attention
#define NCHK (L/KCH)   // 16
#define PKS 68         // Ks pitch (floats): conflict-free float4 key-major reads
#define PVS 66         // Vs pitch (floats): conflict-free float2 d-major reads

// Cumsum chunking
#define NCH 128
#define CHUNK (L/NCH)  // 16

// -------- scratch (device globals; no allocation allowed) --------
__device__ float g_M[BH * L];
__device__ int   g_Mtop[BH * U];
__device__ float g_pm[BH * U * NCHK];
__device__ float g_pl[BH * U * NCHK];
__device__ float g_pacc[BH * U * NCHK * D];
__device__ float g_csum[B * NCH * C];

// ===================== Stage 1: sampled scores -> M =====================
// Block per query q. Thread t = (b=t>>6, h=(t>>3)&7, g=t&7); thread owns dims
// [8g, 8g+8). Samples in batches of 8: 16 independent LDG.128, 8 partial dots,
// 3-stage butterfly reduce-scatter (7 shuffles / 8 samples). Addition tree per
// sample is bit-identical to the xor-1/2/4 butterfly of the passing kernel.
__global__ void __launch_bounds__(256) k_sample_scores(
    const float* __restrict__ Q,
    const float* __restrict__ K,
    const int*   __restrict__ idx)
{
    __shared__ int sidx[SK];
    int q = blockIdx.x;
    int t = threadIdx.x;
    int b = t >> 6;
    int h = (t >> 3) & 7;
    int g = t & 7;

    if (t < SK) sidx[t] = idx[q * SK + t];
    __syncthreads();

    const float* qp = Q + (((size_t)b * L + q) * H + h) * D + g * 8;
    float4 qa = *(const float4*)qp;
    float4 qb = *(const float4*)(qp + 4);

    const size_t hoff = (size_t)h * D + (size_t)g * 8;
    const float* Kb = K + (size_t)b * L * (H * D) + hoff;

    const int b0 = g & 1, b1 = (g >> 1) & 1, b2 = (g >> 2) & 1;

    float mx = -1e30f, sm = 0.f;

    for (int bi = 0; bi < 5; bi++) {
        float4 ka[8], kc[8];
        #pragma unroll
        for (int k = 0; k < 8; k++) {
            const float* kp = Kb + (size_t)sidx[bi * 8 + k] * (H * D);
            ka[k] = *(const float4*)kp;
            kc[k] = *(const float4*)(kp + 4);
        }
        float p[8];
        #pragma unroll
        for (int k = 0; k < 8; k++)
            p[k] = qa.x * ka[k].x + qa.y * ka[k].y + qa.z * ka[k].z + qa.w * ka[k].w
                 + qb.x * kc[k].x + qb.y * kc[k].y + qb.z * kc[k].z + qb.w * kc[k].w;

        float q4[4];
        #pragma unroll
        for (int j = 0; j < 4; j++) {
            float keep = b0 ? p[2 * j + 1] : p[2 * j];
            float send = b0 ? p[2 * j]     : p[2 * j + 1];
            q4[j] = keep + __shfl_xor_sync(0xffffffffu, send, 1);
        }
        float r2[2];
        #pragma unroll
        for (int j = 0; j < 2; j++) {
            float keep = b1 ? q4[2 * j + 1] : q4[2 * j];
            float send = b1 ? q4[2 * j]     : q4[2 * j + 1];
            r2[j] = keep + __shfl_xor_sync(0xffffffffu, send, 2);
        }
        float keep = b2 ? r2[1] : r2[0];
        float send = b2 ? r2[0] : r2[1];
        float d = keep + __shfl_xor_sync(0xffffffffu, send, 4);

        mx = fmaxf(mx, d);
        sm += d;
    }

    #pragma unroll
    for (int o = 1; o < 8; o <<= 1) {
        mx = fmaxf(mx, __shfl_xor_sync(0xffffffffu, mx, o));
        sm += __shfl_xor_sync(0xffffffffu, sm, o);
    }
    if (g == 0)
        g_M[(t >> 3) * L + q] = mx - sm * (1.0f / SK);
}

// ===================== Stage 2: exact top-U: 2 radix passes + rank =========
// Round-12 lesson: ONE MSB-byte pass is useless for same-exponent floats (a
// single byte bin held ~1500 keys, overflowing the candidate cap). Two 8-bit
// passes pin the top 16 bits (relative bin width ~2^-7); candidates matching
// the 16-bit prefix (~40 peak) are ranked exactly by (full key desc, idx asc)
// == jax.lax.top_k tie semantics. Replaces the old passes 3-4.
__device__ __forceinline__ unsigned f2ord(float f)
{
    unsigned u = __float_as_uint(f);
    return (u & 0x80000000u) ? ~u : (u | 0x80000000u);
}

#define CAND 1024

__global__ void __launch_bounds__(1024) k_topk()
{
    __shared__ unsigned keys[L];
    __shared__ int hist[256];
    __shared__ unsigned s_prefix;
    __shared__ int s_rem, s_cnt, s_ecnt;
    __shared__ int cand[CAND];
    __shared__ int tmpi[U];

    int bh = blockIdx.x;
    int t = threadIdx.x;

    unsigned k0 = f2ord(g_M[bh * L + t]);
    unsigned k1 = f2ord(g_M[bh * L + t + 1024]);
    keys[t] = k0;
    keys[t + 1024] = k1;
    if (t == 0) { s_prefix = 0u; s_rem = U; s_cnt = 0; s_ecnt = 0; }
    __syncthreads();

    unsigned mask = 0u;
    #pragma unroll
    for (int shift = 24; shift >= 16; shift -= 8) {
        if (t < 256) hist[t] = 0;
        __syncthreads();
        unsigned pre = s_prefix;
        if ((k0 & mask) == pre) atomicAdd(&hist[(k0 >> shift) & 255], 1);
        if ((k1 & mask) == pre) atomicAdd(&hist[(k1 >> shift) & 255], 1);
        __syncthreads();
        if (t < 32) {
            int rem = s_rem;
            int loc[8], sum = 0;
            #pragma unroll
            for (int j = 0; j < 8; j++) {
                loc[j] = hist[255 - (t * 8 + j)];
                sum += loc[j];
            }
            int pref = sum;
            #pragma unroll
            for (int o = 1; o < 32; o <<= 1) {
                int v = __shfl_up_sync(0xffffffffu, pref, o);
                if (t >= o) pref += v;
            }
            int c = pref - sum;
            #pragma unroll
            for (int j = 0; j < 8; j++) {
                int nc = c + loc[j];
                if (c < rem && nc >= rem) {        // exactly one (lane,j)
                    s_prefix = pre | ((unsigned)(255 - (t * 8 + j)) << shift);
                    s_rem = rem - c;
                }
                c = nc;
            }
        }
        mask |= (0xFFu << shift);
        __syncthreads();
    }

    // top 16 bits pinned. mask == 0xFFFF0000.
    unsigned pre16 = s_prefix;
    int rem = s_rem;
    {
        unsigned hi = k0 & 0xFFFF0000u;
        if (hi > pre16) tmpi[atomicAdd(&s_cnt, 1)] = t;
        else if (hi == pre16) {
            int p = atomicAdd(&s_ecnt, 1);
            if (p < CAND) cand[p] = t;
        }
        hi = k1 & 0xFFFF0000u;
        if (hi > pre16) tmpi[atomicAdd(&s_cnt, 1)] = t + 1024;
        else if (hi == pre16) {
            int p = atomicAdd(&s_ecnt, 1);
            if (p < CAND) cand[p] = t + 1024;
        }
    }
    __syncthreads();

    int ncand = min(s_ecnt, CAND);
    int base = s_cnt;                        // == U - rem by construction
    if (t < ncand) {
        int i = cand[t];
        unsigned k = keys[i];
        int rank = 0;
        for (int j = 0; j < ncand; j++) {
            int cj = cand[j];
            unsigned kj = keys[cj];
            rank += (kj > k) || (kj == k && cj < i);
        }
        if (rank < rem) tmpi[base + rank] = i;
    }
    __syncthreads();

    // rank-sort ascending (indices distinct); g_Mtop consumed as a set
    if (t < U) {
        int v = tmpi[t], r = 0;
        #pragma unroll
        for (int j = 0; j < U; j++) r += (tmpi[j] < v);
        g_Mtop[bh * U + r] = v;
    }
}

// ===================== Stage 3: cumsum of V along L -> out =====================
__global__ void k_cumsum_a(const float* __restrict__ V)
{
    int blk = blockIdx.x;
    int b = blk / NCH, ch = blk % NCH;
    int c = threadIdx.x;
    const float* base = V + ((size_t)b * L + ch * CHUNK) * C + c;
    float s = 0.f;
    #pragma unroll
    for (int l = 0; l < CHUNK; l++) s += base[(size_t)l * C];
    g_csum[((size_t)b * NCH + ch) * C + c] = s;
}

__global__ void k_cumsum_c(const float* __restrict__ V, float* __restrict__ out)
{
    int blk = blockIdx.x;
    int b = blk / NCH, ch = blk % NCH;
    int c = threadIdx.x;
    float run = 0.f;
    for (int j = 0; j < ch; j++)
        run += g_csum[((size_t)b * NCH + j) * C + c];
    const float* vb = V   + ((size_t)b * L + ch * CHUNK) * C + c;
    float*       ob = out + ((size_t)b * L + ch * CHUNK) * C + c;
    #pragma unroll
    for (int l0 = 0; l0 < CHUNK; l0 += 8) {
        float v[8];
        #pragma unroll
        for (int j = 0; j < 8; j++) v[j] = vb[(size_t)(l0 + j) * C];
        #pragma unroll
        for (int j = 0; j < 8; j++) {
            run += v[j];
            ob[(size_t)(l0 + j) * C] = run;
        }
    }
}

// ===================== Stage 4: dense attention partials =====================
__global__ void __launch_bounds__(256) k_attn_partial(
    const float* __restrict__ Q,
    const float* __restrict__ K,
    const float* __restrict__ V)
{
    extern __shared__ float smf[];
    float* Ks = smf;                       // KCH * PKS
    float* Vs = Ks + KCH * PKS;            // KCH * PVS
    float* Qs = Vs + KCH * PVS;            // U * D
    float* pb = Qs + U * D;                // 8 warps * 5 q * 128 k
    int*   ps = (int*)(pb + 8 * 5 * KCH);  // U

    int bh = blockIdx.x >> 4;
    int ch = blockIdx.x & 15;
    int b = bh >> 3, h = bh & 7;
    int t = threadIdx.x;
    int k0 = ch * KCH;

    for (int i = t; i < KCH * D; i += 256) {
        int r = i >> 6, d = i & 63;
        size_t gidx = (((size_t)b * L + (k0 + r)) * H + h) * D + d;
        Ks[r * PKS + d] = K[gidx];
        Vs[r * PVS + d] = V[gidx];
    }
    if (t < U) ps[t] = g_Mtop[bh * U + t];
    __syncthreads();
    for (int i = t; i < U * D; i += 256) {
        int u = i >> 6, d = i & 63;
        Qs[i] = Q[(((size_t)b * L + ps[u]) * H + h) * D + d];
    }
    __syncthreads();

    int w = t >> 5, lane = t & 31;
    const float4* Qb = (const float4*)Qs;

    // whole-warp causal skip (ps sorted ascending; no block barriers below)
    if (ps[w * 5 + 4] < k0) {
        #pragma unroll
        for (int q = 0; q < 5; q++) {
            int pi = (bh * U + w * 5 + q) * NCHK + ch;
            if (lane == 0) { g_pm[pi] = -1e30f; g_pl[pi] = 0.f; }
            *(float2*)&g_pacc[(size_t)pi * D + 2 * lane] = make_float2(0.f, 0.f);
        }
        return;
    }

    float s4[5][4];
    #pragma unroll
    for (int q = 0; q < 5; q++)
        #pragma unroll
        for (int g = 0; g < 4; g++) s4[q][g] = 0.f;

    #pragma unroll 4
    for (int i = 0; i < 16; i++) {
        float4 kk[4];
        #pragma unroll
        for (int g = 0; g < 4; g++)
            kk[g] = *(const float4*)&Ks[(g * 32 + lane) * PKS + 4 * i];
        #pragma unroll
        for (int q = 0; q < 5; q++) {
            float4 qv = Qb[(w * 5 + q) * 16 + i];
            #pragma unroll
            for (int g = 0; g < 4; g++)
                s4[q][g] += qv.x * kk[g].x + qv.y * kk[g].y
                          + qv.z * kk[g].z + qv.w * kk[g].w;
        }
    }

    #pragma unroll
    for (int q = 0; q < 5; q++) {
        int u = w * 5 + q;
        int p = ps[u];
        float sc[4]; bool ok[4];
        float m = -1e30f;
        #pragma unroll
        for (int g = 0; g < 4; g++) {
            sc[g] = s4[q][g] * 0.125f;             // 1/sqrt(64)
            ok[g] = (k0 + g * 32 + lane) <= p;
            m = fmaxf(m, ok[g] ? sc[g] : -1e30f);
        }
        #pragma unroll
        for (int o = 16; o; o >>= 1)
            m = fmaxf(m, __shfl_xor_sync(0xffffffffu, m, o));
        float l = 0.f;
        #pragma unroll
        for (int g = 0; g < 4; g++) {
            float pv = ok[g] ? __expf(sc[g] - m) : 0.f;
            l += pv;
            pb[w * (5 * KCH) + q * KCH + g * 32 + lane] = pv;
        }
        #pragma unroll
        for (int o = 16; o; o >>= 1)
            l += __shfl_xor_sync(0xffffffffu, l, o);
        if (lane == 0) {
            int pi = (bh * U + u) * NCHK + ch;
            g_pm[pi] = m;
            g_pl[pi] = l;
        }
    }
    __syncwarp();

    float2 acc[5];
    #pragma unroll
    for (int q = 0; q < 5; q++) acc[q] = make_float2(0.f, 0.f);

    #pragma unroll 4
    for (int k = 0; k < KCH; k += 4) {
        float2 v0 = *(const float2*)&Vs[(k + 0) * PVS + 2 * lane];
        float2 v1 = *(const float2*)&Vs[(k + 1) * PVS + 2 * lane];
        float2 v2 = *(const float2*)&Vs[(k + 2) * PVS + 2 * lane];
        float2 v3 = *(const float2*)&Vs[(k + 3) * PVS + 2 * lane];
        #pragma unroll
        for (int q = 0; q < 5; q++) {
            float4 pq = *(const float4*)&pb[w * (5 * KCH) + q * KCH + k];
            acc[q].x += pq.x * v0.x + pq.y * v1.x + pq.z * v2.x + pq.w * v3.x;
            acc[q].y += pq.x * v0.y + pq.y * v1.y + pq.z * v2.y + pq.w * v3.y;
        }
    }

    #pragma unroll
    for (int q = 0; q < 5; q++) {
        int u = w * 5 + q;
        int pi = (bh * U + u) * NCHK + ch;
        *(float2*)&g_pacc[(size_t)pi * D + 2 * lane] = acc[q];
    }
}

// ===================== Stage 5: combine partials, scatter rows =====================
__global__ void k_attn_reduce(float* __restrict__ out)
{
    int task = blockIdx.x * (blockDim.x >> 5) + (threadIdx.x >> 5);
    if (task >= BH * U) return;
    int lane = threadIdx.x & 31;
    int bh = task / U, u = task % U;
    int b = bh >> 3, h = bh & 7;

    float m = -1e30f;
    #pragma unroll
    for (int c = 0; c < NCHK; c++) m = fmaxf(m, g_pm[task * NCHK + c]);
    float Lsum = 0.f;
    float2 a = make_float2(0.f, 0.f);
    #pragma unroll
    for (int c = 0; c < NCHK; c++) {
        float wgt = __expf(g_pm[task * NCHK + c] - m);
        Lsum += g_pl[task * NCHK + c] * wgt;
        float2 pa = *(const float2*)&g_pacc[(size_t)(task * NCHK + c) * D + 2 * lane];
        a.x += pa.x * wgt;
        a.y += pa.y * wgt;
    }
    float inv = 1.0f / Lsum;
    int p = g_Mtop[bh * U + u];
    size_t o = (((size_t)b * L + p) * H + h) * D + 2 * lane;
    out[o + 0] = a.x * inv;
    out[o + 1] = a.y * inv;
}

// ===================== launch =====================
extern "C" void kernel_launch(void* const* d_in, const int* in_sizes, int n_in,
                              void* d_out, int out_size)
{
    const float* Q   = (const float*)d_in[0];
    const float* K   = (const float*)d_in[1];
    const float* V   = (const float*)d_in[2];
    const int*   idx = (const int*)d_in[3];
    float* out = (float*)d_out;

    // One-time host-side resources (no device memory involved).
    static cudaStream_t s2 = nullptr;
    static cudaEvent_t evFork = nullptr, evJoin = nullptr;
    if (!s2) {
        cudaStreamCreateWithFlags(&s2, cudaStreamNonBlocking);
        cudaEventCreateWithFlags(&evFork, cudaEventDisableTiming);
        cudaEventCreateWithFlags(&evJoin, cudaEventDisableTiming);
    }

    const int smem_a = (KCH * PKS + KCH * PVS + U * D + 8 * 5 * KCH) * (int)sizeof(float)
                     + U * (int)sizeof(int);
    cudaFuncSetAttribute(k_attn_partial, cudaFuncAttributeMaxDynamicSharedMemorySize, smem_a);

    // Fork: cumsum chain on side stream (independent of sample/topk/attn).
    cudaEventRecord(evFork, 0);
    cudaStreamWaitEvent(s2, evFork, 0);
    k_cumsum_a<<<B * NCH, C, 0, s2>>>(V);
    k_cumsum_c<<<B * NCH, C, 0, s2>>>(V, out);
    cudaEventRecord(evJoin, s2);

    // Main chain on default stream.
    k_sample_scores<<<L, 256>>>(Q, K, idx);
    k_topk<<<BH, 1024>>>();
    k_attn_partial<<<BH * NCHK, 256, smem_a>>>(Q, K, V);

    // Join: reduce overwrites the selected rows of out written by cumsum_c.
    cudaStreamWaitEvent(0, evJoin, 0);
    k_attn_reduce<<<(BH * U) / 8, 256>>>(out);
}